// round 11
// baseline (speedup 1.0000x reference)
#include <cuda_runtime.h>
#include <cuda_bf16.h>
#include <mma.h>
#include <cstdint>
#include <type_traits>

typedef __nv_bfloat16 bf;
typedef __nv_bfloat162 bf2;
namespace wm = nvcuda::wmma;
using AccFrag = wm::fragment<wm::accumulator, 16, 16, 16, float>;

#define BATCH 16
#define TLEN  4096
#define DIM   512
#define NROWS 65536              // time-major rows r = t*16 + b
#define GROWS 256                // rows per group (16 t-steps x 16 batch)
#define NG    256
#define DD2   (DIM*DIM)          // 262144
#define GR2   (GROWS*GROWS)
#define LRW   0.01f

// ---------------- device scratch ----------------
__device__ __align__(256) bf g_Xh[(size_t)NROWS*DIM];
__device__ __align__(256) bf g_Xl[(size_t)NROWS*DIM];
__device__ __align__(256) bf g_Wh[3*DD2];
__device__ __align__(256) bf g_Wl[3*DD2];
__device__ __align__(256) bf g_Qh[(size_t)NROWS*DIM];
__device__ __align__(256) bf g_Ql[(size_t)NROWS*DIM];
__device__ __align__(256) bf g_Kh[(size_t)NROWS*DIM];
__device__ __align__(256) bf g_Kl[(size_t)NROWS*DIM];
__device__ __align__(256) bf g_Vh[(size_t)NROWS*DIM];
__device__ __align__(256) bf g_Vl[(size_t)NROWS*DIM];
__device__ __align__(256) float g_U[(size_t)NG*DD2];
__device__ __align__(256) bf g_Sh[(size_t)NG*DD2];
__device__ __align__(256) bf g_Sl[(size_t)NG*DD2];
__device__ __align__(256) bf g_Sch[(size_t)NG*GR2];
__device__ __align__(256) bf g_Scl[(size_t)NG*GR2];

#define POOL_BYTES 40960   // 4 x 10KB tile arrays; epilogue staging aliases it

// ---------------------------------------------------------------------------
// 128x128 GEMM core, wmma bf16 hi/lo fused 3-product, BK=32, single buffer.
// 128 threads, 4 warps in 2x2 grid, warp tile 64x64 = 4x4 fragments
// (halves smem fragment-read traffic per MMA vs 64x32 warp tiles).
//   AT=false: A stored [m][k] k-contig (row_major frag)
//   AT=true : A stored [k][m] m-contig (col_major frag)
//   BT=false: B stored [n][k] k-contig (col_major frag)  -- NT
//   BT=true : B stored [k][n] n-contig (row_major frag)  -- NN
// ---------------------------------------------------------------------------
template <bool AT, bool BT>
__device__ __forceinline__ void gemm_core(char* smpool,
    const bf* __restrict__ Ah, const bf* __restrict__ Al, size_t lda,
    const bf* __restrict__ Bh, const bf* __restrict__ Bl, size_t ldb,
    int nktp, AccFrag acc[4][4])
{
    constexpr int ALD = AT ? 136 : 40;   // AT tile: 32x136, else 128x40
    constexpr int BLD = BT ? 136 : 40;
    bf* Ash = (bf*)(smpool);
    bf* Asl = (bf*)(smpool + 10240);
    bf* Bsh = (bf*)(smpool + 20480);
    bf* Bsl = (bf*)(smpool + 30720);

    const int tid = threadIdx.x;
    const int w   = tid >> 5;
    const int wmi = w >> 1, wni = w & 1;

    // loader: each thread moves 4x uint4 (32 bf) per array per chunk
    const int ar  = AT ? (tid >> 2) : tid;          // row in tile
    const int acb = AT ? (tid & 3) * 32 : 0;        // col base (elems)
    const int br  = BT ? (tid >> 2) : tid;
    const int bcb = BT ? (tid & 3) * 32 : 0;
    const int aso = ar * ALD + acb;
    const int bso = br * BLD + bcb;

    auto agof = [&](int kt, int j) -> size_t {
        return AT ? (size_t)(kt * 32 + ar) * lda + acb + j * 8
                  : (size_t)ar * lda + kt * 32 + j * 8;
    };
    auto bgof = [&](int kt, int j) -> size_t {
        return BT ? (size_t)(kt * 32 + br) * ldb + bcb + j * 8
                  : (size_t)br * ldb + kt * 32 + j * 8;
    };

#pragma unroll
    for (int mt = 0; mt < 4; mt++)
#pragma unroll
        for (int n2 = 0; n2 < 4; n2++)
            wm::fill_fragment(acc[mt][n2], 0.0f);

    using ALay = typename std::conditional<AT, wm::col_major, wm::row_major>::type;
    using BLay = typename std::conditional<BT, wm::row_major, wm::col_major>::type;

    for (int kt = 0; kt < nktp; ++kt) {
        __syncthreads();   // previous chunk fully consumed
#pragma unroll
        for (int j = 0; j < 4; j++) {
            *(uint4*)(&Ash[aso + j * 8]) = *(const uint4*)(Ah + agof(kt, j));
            *(uint4*)(&Asl[aso + j * 8]) = *(const uint4*)(Al + agof(kt, j));
            *(uint4*)(&Bsh[bso + j * 8]) = *(const uint4*)(Bh + bgof(kt, j));
            *(uint4*)(&Bsl[bso + j * 8]) = *(const uint4*)(Bl + bgof(kt, j));
        }
        __syncthreads();

#pragma unroll
        for (int kk = 0; kk < 2; kk++) {
            wm::fragment<wm::matrix_b, 16, 16, 16, bf, BLay> bfh[4], bfl[4];
#pragma unroll
            for (int n2 = 0; n2 < 4; n2++) {
                int n0 = wni * 64 + n2 * 16;
                int off = BT ? (kk * 16 * BLD + n0) : (n0 * BLD + kk * 16);
                wm::load_matrix_sync(bfh[n2], &Bsh[off], BLD);
                wm::load_matrix_sync(bfl[n2], &Bsl[off], BLD);
            }
#pragma unroll
            for (int mt = 0; mt < 4; mt++) {
                wm::fragment<wm::matrix_a, 16, 16, 16, bf, ALay> afh, afl;
                int m0 = wmi * 64 + mt * 16;
                int off = AT ? (kk * 16 * ALD + m0) : (m0 * ALD + kk * 16);
                wm::load_matrix_sync(afh, &Ash[off], ALD);
                wm::load_matrix_sync(afl, &Asl[off], ALD);
#pragma unroll
                for (int n2 = 0; n2 < 4; n2++) {
                    wm::mma_sync(acc[mt][n2], afh, bfh[n2], acc[mt][n2]);
                    wm::mma_sync(acc[mt][n2], afl, bfh[n2], acc[mt][n2]);
                    wm::mma_sync(acc[mt][n2], afh, bfl[n2], acc[mt][n2]);
                }
            }
        }
    }
    __syncthreads();   // protect pool before epilogue aliases it
}

// Epilogue: stage each frag through smem (aliases pool), then scalar writes.
// Exposes: row (0..127 tile-local), col (0..127 tile-local), v (float).
#define EPILOGUE(...)                                                     \
  { float* stg = (float*)(smpool) + (threadIdx.x >> 5) * 320;             \
    const int lane = threadIdx.x & 31;                                    \
    const int w = threadIdx.x >> 5, wm_ = w >> 1, wn_ = w & 1;            \
    for (int mt = 0; mt < 4; mt++)                                        \
      for (int n2 = 0; n2 < 4; n2++) {                                    \
        wm::store_matrix_sync(stg, acc[mt][n2], 20, wm::mem_row_major);   \
        __syncwarp();                                                     \
        _Pragma("unroll")                                                 \
        for (int e = 0; e < 8; e++) {                                     \
          int lr = 2 * e + (lane >> 4); int lc = lane & 15;               \
          int row = wm_ * 64 + mt * 16 + lr;                              \
          int col = wn_ * 64 + n2 * 16 + lc;                              \
          float v = stg[lr * 20 + lc];                                    \
          __VA_ARGS__                                                     \
        }                                                                 \
        __syncwarp();                                                     \
      } }

#define DECL_POOL __shared__ __align__(16) char smpool[POOL_BYTES]

__device__ __forceinline__ void split1(bf* Oh, bf* Ol, size_t idx, float v) {
    bf h = __float2bfloat16(v);
    Oh[idx] = h;
    Ol[idx] = __float2bfloat16(v - __bfloat162float(h));
}
__device__ __forceinline__ void split_store(bf* Oh, bf* Ol, size_t idx,
                                            float v0, float v1) {
    bf h0 = __float2bfloat16(v0), h1 = __float2bfloat16(v1);
    bf2 ph; ph.x = h0; ph.y = h1;
    bf2 pl; pl.x = __float2bfloat16(v0 - __bfloat162float(h0));
            pl.y = __float2bfloat16(v1 - __bfloat162float(h1));
    *(bf2*)(Oh + idx) = ph;
    *(bf2*)(Ol + idx) = pl;
}

// ---------------- conversion / scan ----------------------------------------
__global__ void conv_x_kernel(const float* __restrict__ x) {
    int i = blockIdx.x * 256 + threadIdx.x;       // over NROWS*DIM/4
    int r = i >> 7;
    int d = (i & 127) * 4;
    int tt = r >> 4, bb = r & 15;
    float4 v = *(const float4*)(x + (size_t)(bb * TLEN + tt) * DIM + d);
    size_t o = (size_t)r * DIM + d;
    split_store(g_Xh, g_Xl, o,     v.x, v.y);
    split_store(g_Xh, g_Xl, o + 2, v.z, v.w);
}

__global__ void conv_w_kernel(const float* __restrict__ Wq,
                              const float* __restrict__ Wk,
                              const float* __restrict__ Wv) {
    int i = blockIdx.x * 256 + threadIdx.x;       // over 3*DD2/4
    int z = i >> 16;
    int off = (i & 65535) * 4;
    const float* src = (z == 0) ? Wq : (z == 1) ? Wk : Wv;
    float4 v = *(const float4*)(src + off);
    size_t o = (size_t)z * DD2 + off;
    split_store(g_Wh, g_Wl, o,     v.x, v.y);
    split_store(g_Wh, g_Wl, o + 2, v.z, v.w);
}

__global__ void scan_kernel(const float* __restrict__ mem0) {
    int i4 = (blockIdx.x * 256 + threadIdx.x) * 4;    // over DD2
    float4 acc = *(const float4*)(mem0 + i4);
    for (int g = 0; g < NG; g++) {
        size_t off = (size_t)g * DD2 + i4;
        float4 u = *(const float4*)(g_U + off);
        split_store(g_Sh, g_Sl, off,     acc.x, acc.y);
        split_store(g_Sh, g_Sl, off + 2, acc.z, acc.w);
        acc.x = fmaf(LRW, u.x, acc.x);
        acc.y = fmaf(LRW, u.y, acc.y);
        acc.z = fmaf(LRW, u.z, acc.z);
        acc.w = fmaf(LRW, u.w, acc.w);
    }
}

// ---------------- GEMM kernels ---------------------------------------------
__global__ __launch_bounds__(128, 2) void gemm_qkv_kernel() {
    DECL_POOL;
    int mt0 = blockIdx.x, nt0 = blockIdx.y, z = blockIdx.z;
    const bf* Ah = g_Xh + (size_t)mt0 * 128 * DIM;
    const bf* Al = g_Xl + (size_t)mt0 * 128 * DIM;
    const bf* Bh = g_Wh + (size_t)z * DD2 + (size_t)nt0 * 128 * DIM;
    const bf* Bl = g_Wl + (size_t)z * DD2 + (size_t)nt0 * 128 * DIM;
    AccFrag acc[4][4];
    gemm_core<false, false>(smpool, Ah, Al, DIM, Bh, Bl, DIM, DIM / 32, acc);
    bf* Oh = (z == 0) ? g_Qh : (z == 1) ? g_Kh : g_Vh;
    bf* Ol = (z == 0) ? g_Ql : (z == 1) ? g_Kl : g_Vl;
    EPILOGUE(
        size_t idx = (size_t)(mt0 * 128 + row) * DIM + nt0 * 128 + col;
        split1(Oh, Ol, idx, v);
    )
}

// U_g[d,e] = sum_r V[r,d] K[r,e]   -- A = V read transposed, B = K read NN
__global__ __launch_bounds__(128, 2) void gemm_u_kernel() {
    DECL_POOL;
    int d0 = blockIdx.x * 128, e0 = blockIdx.y * 128, g = blockIdx.z;
    const bf* Ah = g_Vh + (size_t)(g * GROWS) * DIM + d0;
    const bf* Al = g_Vl + (size_t)(g * GROWS) * DIM + d0;
    const bf* Bh = g_Kh + (size_t)(g * GROWS) * DIM + e0;
    const bf* Bl = g_Kl + (size_t)(g * GROWS) * DIM + e0;
    AccFrag acc[4][4];
    gemm_core<true, true>(smpool, Ah, Al, DIM, Bh, Bl, DIM, GROWS / 32, acc);
    float* U = g_U + (size_t)g * DD2;
    EPILOGUE(
        U[(size_t)(d0 + row) * DIM + e0 + col] = v;
    )
}

__global__ __launch_bounds__(128, 2) void gemm_inter_kernel(float* __restrict__ out) {
    DECL_POOL;
    int mt0 = blockIdx.x, nt0 = blockIdx.y;
    int g = mt0 >> 1;
    const bf* Ah = g_Qh + (size_t)mt0 * 128 * DIM;
    const bf* Al = g_Ql + (size_t)mt0 * 128 * DIM;
    const bf* Bh = g_Sh + (size_t)g * DD2 + (size_t)nt0 * 128 * DIM;
    const bf* Bl = g_Sl + (size_t)g * DD2 + (size_t)nt0 * 128 * DIM;
    AccFrag acc[4][4];
    gemm_core<false, false>(smpool, Ah, Al, DIM, Bh, Bl, DIM, DIM / 32, acc);
    EPILOGUE(
        int r = mt0 * 128 + row;
        int tt = r >> 4; int bb = r & 15;
        out[(size_t)(bb * TLEN + tt) * DIM + nt0 * 128 + col] = v;
    )
}

__global__ __launch_bounds__(128, 2) void gemm_score_kernel() {
    DECL_POOL;
    int id = blockIdx.x;                 // 0:(0,0) 1:(1,0) 2:(1,1)
    int ti = (id == 0) ? 0 : 1;
    int tj = (id == 2) ? 1 : 0;
    int g = blockIdx.y;
    const bf* Ah = g_Qh + (size_t)(g * GROWS + ti * 128) * DIM;
    const bf* Al = g_Ql + (size_t)(g * GROWS + ti * 128) * DIM;
    const bf* Bh = g_Kh + (size_t)(g * GROWS + tj * 128) * DIM;
    const bf* Bl = g_Kl + (size_t)(g * GROWS + tj * 128) * DIM;
    AccFrag acc[4][4];
    gemm_core<false, false>(smpool, Ah, Al, DIM, Bh, Bl, DIM, DIM / 32, acc);
    bf* Sch = g_Sch + (size_t)g * GR2;
    bf* Scl = g_Scl + (size_t)g * GR2;
    EPILOGUE(
        int rr = ti * 128 + row;
        int ss = tj * 128 + col;
        float m = ((ss >> 4) <= (rr >> 4)) ? LRW * v : 0.0f;
        split1(Sch, Scl, (size_t)rr * GROWS + ss, m);
    )
}

// out[r,d] += sum_s Sc[r,s] V[s,d]  -- B = V read NN
__global__ __launch_bounds__(128, 2) void gemm_av_kernel(float* __restrict__ out) {
    DECL_POOL;
    int ti = blockIdx.x;                 // 0..1 row tile within group
    int nt0 = blockIdx.y;                // 0..3
    int g = blockIdx.z;
    const bf* Ah = g_Sch + (size_t)g * GR2 + (size_t)ti * 128 * GROWS;
    const bf* Al = g_Scl + (size_t)g * GR2 + (size_t)ti * 128 * GROWS;
    const bf* Bh = g_Vh + (size_t)(g * GROWS) * DIM + nt0 * 128;
    const bf* Bl = g_Vl + (size_t)(g * GROWS) * DIM + nt0 * 128;
    AccFrag acc[4][4];
    gemm_core<false, true>(smpool, Ah, Al, GROWS, Bh, Bl, DIM, 4 * (ti + 1), acc);
    EPILOGUE(
        int r = g * GROWS + ti * 128 + row;
        int tt = r >> 4; int bb = r & 15;
        size_t idx = (size_t)(bb * TLEN + tt) * DIM + nt0 * 128 + col;
        out[idx] += v;
    )
}

// ---------------------------------------------------------------------------
extern "C" void kernel_launch(void* const* d_in, const int* in_sizes, int n_in,
                              void* d_out, int out_size) {
    (void)in_sizes; (void)n_in; (void)out_size;
    const float* x  = (const float*)d_in[0];
    const float* Wq = (const float*)d_in[1];
    const float* Wk = (const float*)d_in[2];
    const float* Wv = (const float*)d_in[3];
    const float* m0 = (const float*)d_in[4];
    float* out = (float*)d_out;

    conv_x_kernel<<<32768, 256>>>(x);
    conv_w_kernel<<<768, 256>>>(Wq, Wk, Wv);
    gemm_qkv_kernel<<<dim3(512, 4, 3), 128>>>();
    gemm_u_kernel<<<dim3(4, 4, 256), 128>>>();
    scan_kernel<<<256, 256>>>(m0);
    gemm_score_kernel<<<dim3(3, 256), 128>>>();
    gemm_inter_kernel<<<dim3(512, 4), 128>>>(out);
    gemm_av_kernel<<<dim3(2, 4, 256), 128>>>(out);
}

// round 12
// speedup vs baseline: 1.7290x; 1.7290x over previous
#include <cuda_runtime.h>
#include <cuda_bf16.h>
#include <mma.h>
#include <cstdint>
#include <type_traits>

typedef __nv_bfloat16 bf;
typedef __nv_bfloat162 bf2;
namespace wm = nvcuda::wmma;
using AccFrag = wm::fragment<wm::accumulator, 16, 16, 16, float>;

#define BATCH 16
#define TLEN  4096
#define DIM   512
#define NROWS 65536              // time-major rows r = t*16 + b
#define GROWS 256                // rows per group (16 t-steps x 16 batch)
#define NG    256
#define DD2   (DIM*DIM)          // 262144
#define GR2   (GROWS*GROWS)
#define LRW   0.01f

// ---------------- device scratch ----------------
__device__ __align__(256) bf g_Xh[(size_t)NROWS*DIM];
__device__ __align__(256) bf g_Xl[(size_t)NROWS*DIM];
__device__ __align__(256) bf g_Wh[3*DD2];
__device__ __align__(256) bf g_Wl[3*DD2];
__device__ __align__(256) bf g_Qh[(size_t)NROWS*DIM];
__device__ __align__(256) bf g_Ql[(size_t)NROWS*DIM];
__device__ __align__(256) bf g_Kh[(size_t)NROWS*DIM];
__device__ __align__(256) bf g_Kl[(size_t)NROWS*DIM];
__device__ __align__(256) bf g_Vh[(size_t)NROWS*DIM];
__device__ __align__(256) bf g_Vl[(size_t)NROWS*DIM];
__device__ __align__(256) float g_U[(size_t)NG*DD2];
__device__ __align__(256) bf g_Sh[(size_t)NG*DD2];
__device__ __align__(256) bf g_Sl[(size_t)NG*DD2];
__device__ __align__(256) bf g_Sch[(size_t)NG*GR2];
__device__ __align__(256) bf g_Scl[(size_t)NG*GR2];

// 2 stages x 4 arrays x 6KB = 48KB static; epilogue staging aliases stage 0
#define POOL_BYTES 49152
#define STAGE_BYTES 24576
#define ARR_BYTES 6144

// ---------------------------------------------------------------------------
// 128x128 GEMM core, wmma bf16 hi/lo fused 3-product, BK=16,
// DOUBLE-BUFFERED smem + register prefetch: 1 barrier per chunk, global
// load latency hidden under the MMA phase.
//   AT=false: A stored [m][k] k-contig (row_major frag)
//   AT=true : A stored [k][m] m-contig (col_major frag)
//   BT=false: B stored [n][k] k-contig (col_major frag)  -- NT
//   BT=true : B stored [k][n] n-contig (row_major frag)  -- NN
// 256 threads, 8 warps 2x4, warp tile 64x32 = 4x2 fragments.
// ---------------------------------------------------------------------------
template <bool AT, bool BT>
__device__ __forceinline__ void gemm_core(char* smpool,
    const bf* __restrict__ Ah, const bf* __restrict__ Al, size_t lda,
    const bf* __restrict__ Bh, const bf* __restrict__ Bl, size_t ldb,
    int nktp, AccFrag acc[4][2])
{
    constexpr int ALD = AT ? 136 : 24;   // AT tile: 16x136, else 128x24
    constexpr int BLD = BT ? 136 : 24;

    const int tid = threadIdx.x;
    const int w   = tid >> 5;
    const int wmi = w >> 2, wni = w & 3;

    // loader: each thread moves 1 uint4 (8 bf) per array per chunk
    const int ar  = AT ? (tid >> 4) : (tid >> 1);
    const int acb = (AT ? (tid & 15) : (tid & 1)) * 8;
    const int br  = BT ? (tid >> 4) : (tid >> 1);
    const int bcb = (BT ? (tid & 15) : (tid & 1)) * 8;
    const int aso = (ar * ALD + acb) * 2;   // byte offsets
    const int bso = (br * BLD + bcb) * 2;

    auto agof = [&](int kt) -> size_t {
        return AT ? (size_t)(kt * 16 + ar) * lda + acb
                  : (size_t)ar * lda + kt * 16 + acb;
    };
    auto bgof = [&](int kt) -> size_t {
        return BT ? (size_t)(kt * 16 + br) * ldb + bcb
                  : (size_t)br * ldb + kt * 16 + bcb;
    };

#pragma unroll
    for (int mt = 0; mt < 4; mt++)
#pragma unroll
        for (int n2 = 0; n2 < 2; n2++)
            wm::fill_fragment(acc[mt][n2], 0.0f);

    using ALay = typename std::conditional<AT, wm::col_major, wm::row_major>::type;
    using BLay = typename std::conditional<BT, wm::row_major, wm::col_major>::type;

    uint4 pah = *(const uint4*)(Ah + agof(0));
    uint4 pal = *(const uint4*)(Al + agof(0));
    uint4 pbh = *(const uint4*)(Bh + bgof(0));
    uint4 pbl = *(const uint4*)(Bl + bgof(0));

    auto sts = [&](int buf, uint4 a_h, uint4 a_l, uint4 b_h, uint4 b_l) {
        char* bb = smpool + buf * STAGE_BYTES;
        *(uint4*)(bb + aso)                 = a_h;
        *(uint4*)(bb + ARR_BYTES + aso)     = a_l;
        *(uint4*)(bb + 2 * ARR_BYTES + bso) = b_h;
        *(uint4*)(bb + 3 * ARR_BYTES + bso) = b_l;
    };

    sts(0, pah, pal, pbh, pbl);
    __syncthreads();

    for (int kt = 0; kt < nktp; ++kt) {
        if (kt + 1 < nktp) {   // prefetch next chunk; hides under MMAs below
            pah = *(const uint4*)(Ah + agof(kt + 1));
            pal = *(const uint4*)(Al + agof(kt + 1));
            pbh = *(const uint4*)(Bh + bgof(kt + 1));
            pbl = *(const uint4*)(Bl + bgof(kt + 1));
        }
        char* bb = smpool + (kt & 1) * STAGE_BYTES;
        bf* Ash = (bf*)(bb);
        bf* Asl = (bf*)(bb + ARR_BYTES);
        bf* Bsh = (bf*)(bb + 2 * ARR_BYTES);
        bf* Bsl = (bf*)(bb + 3 * ARR_BYTES);

        wm::fragment<wm::matrix_b, 16, 16, 16, bf, BLay> bfh[2], bfl[2];
#pragma unroll
        for (int n2 = 0; n2 < 2; n2++) {
            int n0 = wni * 32 + n2 * 16;
            int off = BT ? n0 : n0 * BLD;
            wm::load_matrix_sync(bfh[n2], &Bsh[off], BLD);
            wm::load_matrix_sync(bfl[n2], &Bsl[off], BLD);
        }
#pragma unroll
        for (int mt = 0; mt < 4; mt++) {
            wm::fragment<wm::matrix_a, 16, 16, 16, bf, ALay> afh, afl;
            int m0 = wmi * 64 + mt * 16;
            int off = AT ? m0 : m0 * ALD;
            wm::load_matrix_sync(afh, &Ash[off], ALD);
            wm::load_matrix_sync(afl, &Asl[off], ALD);
#pragma unroll
            for (int n2 = 0; n2 < 2; n2++) {
                wm::mma_sync(acc[mt][n2], afh, bfh[n2], acc[mt][n2]);
                wm::mma_sync(acc[mt][n2], afl, bfh[n2], acc[mt][n2]);
                wm::mma_sync(acc[mt][n2], afh, bfl[n2], acc[mt][n2]);
            }
        }
        if (kt + 1 < nktp) {
            sts((kt + 1) & 1, pah, pal, pbh, pbl);
            __syncthreads();
        }
    }
    __syncthreads();   // protect pool before epilogue aliases it
}

// Epilogue: stage each frag through smem (aliases pool), then scalar writes.
// Exposes: row (0..127 tile-local), col (0..127 tile-local), v (float).
#define EPILOGUE(...)                                                     \
  { float* stg = (float*)(smpool) + (threadIdx.x >> 5) * 320;             \
    const int lane = threadIdx.x & 31;                                    \
    const int w = threadIdx.x >> 5, wm_ = w >> 2, wn_ = w & 3;            \
    for (int mt = 0; mt < 4; mt++)                                        \
      for (int n2 = 0; n2 < 2; n2++) {                                    \
        wm::store_matrix_sync(stg, acc[mt][n2], 20, wm::mem_row_major);   \
        __syncwarp();                                                     \
        _Pragma("unroll")                                                 \
        for (int e = 0; e < 8; e++) {                                     \
          int lr = 2 * e + (lane >> 4); int lc = lane & 15;               \
          int row = wm_ * 64 + mt * 16 + lr;                              \
          int col = wn_ * 32 + n2 * 16 + lc;                              \
          float v = stg[lr * 20 + lc];                                    \
          __VA_ARGS__                                                     \
        }                                                                 \
        __syncwarp();                                                     \
      } }

#define DECL_POOL __shared__ __align__(16) char smpool[POOL_BYTES]

__device__ __forceinline__ void split1(bf* Oh, bf* Ol, size_t idx, float v) {
    bf h = __float2bfloat16(v);
    Oh[idx] = h;
    Ol[idx] = __float2bfloat16(v - __bfloat162float(h));
}
__device__ __forceinline__ void split_store(bf* Oh, bf* Ol, size_t idx,
                                            float v0, float v1) {
    bf h0 = __float2bfloat16(v0), h1 = __float2bfloat16(v1);
    bf2 ph; ph.x = h0; ph.y = h1;
    bf2 pl; pl.x = __float2bfloat16(v0 - __bfloat162float(h0));
            pl.y = __float2bfloat16(v1 - __bfloat162float(h1));
    *(bf2*)(Oh + idx) = ph;
    *(bf2*)(Ol + idx) = pl;
}

// ---------------- conversion / scan ----------------------------------------
__global__ void conv_x_kernel(const float* __restrict__ x) {
    int i = blockIdx.x * 256 + threadIdx.x;       // over NROWS*DIM/4
    int r = i >> 7;
    int d = (i & 127) * 4;
    int tt = r >> 4, bb = r & 15;
    float4 v = *(const float4*)(x + (size_t)(bb * TLEN + tt) * DIM + d);
    size_t o = (size_t)r * DIM + d;
    split_store(g_Xh, g_Xl, o,     v.x, v.y);
    split_store(g_Xh, g_Xl, o + 2, v.z, v.w);
}

__global__ void conv_w_kernel(const float* __restrict__ Wq,
                              const float* __restrict__ Wk,
                              const float* __restrict__ Wv) {
    int i = blockIdx.x * 256 + threadIdx.x;       // over 3*DD2/4
    int z = i >> 16;
    int off = (i & 65535) * 4;
    const float* src = (z == 0) ? Wq : (z == 1) ? Wk : Wv;
    float4 v = *(const float4*)(src + off);
    size_t o = (size_t)z * DD2 + off;
    split_store(g_Wh, g_Wl, o,     v.x, v.y);
    split_store(g_Wh, g_Wl, o + 2, v.z, v.w);
}

__global__ void scan_kernel(const float* __restrict__ mem0) {
    int i4 = (blockIdx.x * 256 + threadIdx.x) * 4;    // over DD2
    float4 acc = *(const float4*)(mem0 + i4);
    for (int g = 0; g < NG; g++) {
        size_t off = (size_t)g * DD2 + i4;
        float4 u = *(const float4*)(g_U + off);
        split_store(g_Sh, g_Sl, off,     acc.x, acc.y);
        split_store(g_Sh, g_Sl, off + 2, acc.z, acc.w);
        acc.x = fmaf(LRW, u.x, acc.x);
        acc.y = fmaf(LRW, u.y, acc.y);
        acc.z = fmaf(LRW, u.z, acc.z);
        acc.w = fmaf(LRW, u.w, acc.w);
    }
}

// ---------------- GEMM kernels ---------------------------------------------
__global__ __launch_bounds__(256, 2) void gemm_qkv_kernel() {
    DECL_POOL;
    int mt0 = blockIdx.x, nt0 = blockIdx.y, z = blockIdx.z;
    const bf* Ah = g_Xh + (size_t)mt0 * 128 * DIM;
    const bf* Al = g_Xl + (size_t)mt0 * 128 * DIM;
    const bf* Bh = g_Wh + (size_t)z * DD2 + (size_t)nt0 * 128 * DIM;
    const bf* Bl = g_Wl + (size_t)z * DD2 + (size_t)nt0 * 128 * DIM;
    AccFrag acc[4][2];
    gemm_core<false, false>(smpool, Ah, Al, DIM, Bh, Bl, DIM, DIM / 16, acc);
    bf* Oh = (z == 0) ? g_Qh : (z == 1) ? g_Kh : g_Vh;
    bf* Ol = (z == 0) ? g_Ql : (z == 1) ? g_Kl : g_Vl;
    EPILOGUE(
        size_t idx = (size_t)(mt0 * 128 + row) * DIM + nt0 * 128 + col;
        split1(Oh, Ol, idx, v);
    )
}

// U_g[d,e] = sum_r V[r,d] K[r,e]   -- A = V read transposed, B = K read NN
__global__ __launch_bounds__(256, 2) void gemm_u_kernel() {
    DECL_POOL;
    int d0 = blockIdx.x * 128, e0 = blockIdx.y * 128, g = blockIdx.z;
    const bf* Ah = g_Vh + (size_t)(g * GROWS) * DIM + d0;
    const bf* Al = g_Vl + (size_t)(g * GROWS) * DIM + d0;
    const bf* Bh = g_Kh + (size_t)(g * GROWS) * DIM + e0;
    const bf* Bl = g_Kl + (size_t)(g * GROWS) * DIM + e0;
    AccFrag acc[4][2];
    gemm_core<true, true>(smpool, Ah, Al, DIM, Bh, Bl, DIM, GROWS / 16, acc);
    float* U = g_U + (size_t)g * DD2;
    EPILOGUE(
        U[(size_t)(d0 + row) * DIM + e0 + col] = v;
    )
}

__global__ __launch_bounds__(256, 2) void gemm_inter_kernel(float* __restrict__ out) {
    DECL_POOL;
    int mt0 = blockIdx.x, nt0 = blockIdx.y;
    int g = mt0 >> 1;
    const bf* Ah = g_Qh + (size_t)mt0 * 128 * DIM;
    const bf* Al = g_Ql + (size_t)mt0 * 128 * DIM;
    const bf* Bh = g_Sh + (size_t)g * DD2 + (size_t)nt0 * 128 * DIM;
    const bf* Bl = g_Sl + (size_t)g * DD2 + (size_t)nt0 * 128 * DIM;
    AccFrag acc[4][2];
    gemm_core<false, false>(smpool, Ah, Al, DIM, Bh, Bl, DIM, DIM / 16, acc);
    EPILOGUE(
        int r = mt0 * 128 + row;
        int tt = r >> 4; int bb = r & 15;
        out[(size_t)(bb * TLEN + tt) * DIM + nt0 * 128 + col] = v;
    )
}

__global__ __launch_bounds__(256, 2) void gemm_score_kernel() {
    DECL_POOL;
    int id = blockIdx.x;                 // 0:(0,0) 1:(1,0) 2:(1,1)
    int ti = (id == 0) ? 0 : 1;
    int tj = (id == 2) ? 1 : 0;
    int g = blockIdx.y;
    const bf* Ah = g_Qh + (size_t)(g * GROWS + ti * 128) * DIM;
    const bf* Al = g_Ql + (size_t)(g * GROWS + ti * 128) * DIM;
    const bf* Bh = g_Kh + (size_t)(g * GROWS + tj * 128) * DIM;
    const bf* Bl = g_Kl + (size_t)(g * GROWS + tj * 128) * DIM;
    AccFrag acc[4][2];
    gemm_core<false, false>(smpool, Ah, Al, DIM, Bh, Bl, DIM, DIM / 16, acc);
    bf* Sch = g_Sch + (size_t)g * GR2;
    bf* Scl = g_Scl + (size_t)g * GR2;
    EPILOGUE(
        int rr = ti * 128 + row;
        int ss = tj * 128 + col;
        float m = ((ss >> 4) <= (rr >> 4)) ? LRW * v : 0.0f;
        split1(Sch, Scl, (size_t)rr * GROWS + ss, m);
    )
}

// out[r,d] += sum_s Sc[r,s] V[s,d]  -- B = V read NN
__global__ __launch_bounds__(256, 2) void gemm_av_kernel(float* __restrict__ out) {
    DECL_POOL;
    int ti = blockIdx.x;                 // 0..1 row tile within group
    int nt0 = blockIdx.y;                // 0..3
    int g = blockIdx.z;
    const bf* Ah = g_Sch + (size_t)g * GR2 + (size_t)ti * 128 * GROWS;
    const bf* Al = g_Scl + (size_t)g * GR2 + (size_t)ti * 128 * GROWS;
    const bf* Bh = g_Vh + (size_t)(g * GROWS) * DIM + nt0 * 128;
    const bf* Bl = g_Vl + (size_t)(g * GROWS) * DIM + nt0 * 128;
    AccFrag acc[4][2];
    gemm_core<false, true>(smpool, Ah, Al, GROWS, Bh, Bl, DIM, 8 * (ti + 1), acc);
    EPILOGUE(
        int r = g * GROWS + ti * 128 + row;
        int tt = r >> 4; int bb = r & 15;
        size_t idx = (size_t)(bb * TLEN + tt) * DIM + nt0 * 128 + col;
        out[idx] += v;
    )
}

// ---------------------------------------------------------------------------
extern "C" void kernel_launch(void* const* d_in, const int* in_sizes, int n_in,
                              void* d_out, int out_size) {
    (void)in_sizes; (void)n_in; (void)out_size;
    const float* x  = (const float*)d_in[0];
    const float* Wq = (const float*)d_in[1];
    const float* Wk = (const float*)d_in[2];
    const float* Wv = (const float*)d_in[3];
    const float* m0 = (const float*)d_in[4];
    float* out = (float*)d_out;

    conv_x_kernel<<<32768, 256>>>(x);
    conv_w_kernel<<<768, 256>>>(Wq, Wk, Wv);
    gemm_qkv_kernel<<<dim3(512, 4, 3), 256>>>();
    gemm_u_kernel<<<dim3(4, 4, 256), 256>>>();
    scan_kernel<<<256, 256>>>(m0);
    gemm_score_kernel<<<dim3(3, 256), 256>>>();
    gemm_inter_kernel<<<dim3(512, 4), 256>>>(out);
    gemm_av_kernel<<<dim3(2, 4, 256), 256>>>(out);
}

// round 13
// speedup vs baseline: 1.8809x; 1.0879x over previous
#include <cuda_runtime.h>
#include <cuda_bf16.h>
#include <cuda_pipeline.h>
#include <mma.h>
#include <cstdint>
#include <type_traits>

typedef __nv_bfloat16 bf;
typedef __nv_bfloat162 bf2;
namespace wm = nvcuda::wmma;
using AccFrag = wm::fragment<wm::accumulator, 16, 16, 16, float>;

#define BATCH 16
#define TLEN  4096
#define DIM   512
#define NROWS 65536              // time-major rows r = t*16 + b
#define GROWS 256                // rows per group (16 t-steps x 16 batch)
#define NG    256
#define DD2   (DIM*DIM)          // 262144
#define GR2   (GROWS*GROWS)
#define LRW   0.01f

// ---------------- device scratch ----------------
__device__ __align__(256) bf g_Xh[(size_t)NROWS*DIM];
__device__ __align__(256) bf g_Xl[(size_t)NROWS*DIM];
__device__ __align__(256) bf g_Wh[3*DD2];
__device__ __align__(256) bf g_Wl[3*DD2];
__device__ __align__(256) bf g_Qh[(size_t)NROWS*DIM];
__device__ __align__(256) bf g_Ql[(size_t)NROWS*DIM];
__device__ __align__(256) bf g_Kh[(size_t)NROWS*DIM];
__device__ __align__(256) bf g_Kl[(size_t)NROWS*DIM];
__device__ __align__(256) bf g_Vh[(size_t)NROWS*DIM];
__device__ __align__(256) bf g_Vl[(size_t)NROWS*DIM];
__device__ __align__(256) float g_U[(size_t)NG*DD2];
__device__ __align__(256) bf g_Sh[(size_t)NG*DD2];
__device__ __align__(256) bf g_Sl[(size_t)NG*DD2];
__device__ __align__(256) bf g_Sch[(size_t)NG*GR2];
__device__ __align__(256) bf g_Scl[(size_t)NG*GR2];

// 2 stages x 4 arrays x 6KB = 48KB static; epilogue staging aliases stage 0
#define POOL_BYTES 49152
#define STAGE_BYTES 24576
#define ARR_BYTES 6144

// ---------------------------------------------------------------------------
// 128x128 GEMM core, wmma bf16 hi/lo fused 3-product, BK=16,
// DOUBLE-BUFFERED smem with cp.async (__pipeline) copies: the next chunk's
// global->smem copy runs in the background DURING the MMA phase; 1 barrier
// per chunk; no prefetch registers; LDG bypasses L1/RF.
//   AT=false: A stored [m][k] k-contig (row_major frag)
//   AT=true : A stored [k][m] m-contig (col_major frag)
//   BT=false: B stored [n][k] k-contig (col_major frag)  -- NT
//   BT=true : B stored [k][n] n-contig (row_major frag)  -- NN
// 256 threads, 8 warps 2x4, warp tile 64x32 = 4x2 fragments.
// ---------------------------------------------------------------------------
template <bool AT, bool BT>
__device__ __forceinline__ void gemm_core(char* smpool,
    const bf* __restrict__ Ah, const bf* __restrict__ Al, size_t lda,
    const bf* __restrict__ Bh, const bf* __restrict__ Bl, size_t ldb,
    int nktp, AccFrag acc[4][2])
{
    constexpr int ALD = AT ? 136 : 24;   // AT tile: 16x136, else 128x24
    constexpr int BLD = BT ? 136 : 24;

    const int tid = threadIdx.x;
    const int w   = tid >> 5;
    const int wmi = w >> 2, wni = w & 3;

    // loader: each thread copies 1x16B per array per chunk
    const int ar  = AT ? (tid >> 4) : (tid >> 1);
    const int acb = (AT ? (tid & 15) : (tid & 1)) * 8;
    const int br  = BT ? (tid >> 4) : (tid >> 1);
    const int bcb = (BT ? (tid & 15) : (tid & 1)) * 8;
    const int aso = (ar * ALD + acb) * 2;   // byte offsets (16B aligned)
    const int bso = (br * BLD + bcb) * 2;

    auto agof = [&](int kt) -> size_t {
        return AT ? (size_t)(kt * 16 + ar) * lda + acb
                  : (size_t)ar * lda + kt * 16 + acb;
    };
    auto bgof = [&](int kt) -> size_t {
        return BT ? (size_t)(kt * 16 + br) * ldb + bcb
                  : (size_t)br * ldb + kt * 16 + bcb;
    };

    auto issue_copy = [&](int kt, int buf) {
        char* bb = smpool + buf * STAGE_BYTES;
        __pipeline_memcpy_async(bb + aso,                 Ah + agof(kt), 16);
        __pipeline_memcpy_async(bb + ARR_BYTES + aso,     Al + agof(kt), 16);
        __pipeline_memcpy_async(bb + 2 * ARR_BYTES + bso, Bh + bgof(kt), 16);
        __pipeline_memcpy_async(bb + 3 * ARR_BYTES + bso, Bl + bgof(kt), 16);
        __pipeline_commit();
    };

#pragma unroll
    for (int mt = 0; mt < 4; mt++)
#pragma unroll
        for (int n2 = 0; n2 < 2; n2++)
            wm::fill_fragment(acc[mt][n2], 0.0f);

    using ALay = typename std::conditional<AT, wm::col_major, wm::row_major>::type;
    using BLay = typename std::conditional<BT, wm::row_major, wm::col_major>::type;

    issue_copy(0, 0);

    for (int kt = 0; kt < nktp; ++kt) {
        __pipeline_wait_prior(0);   // chunk kt's copy complete
        __syncthreads();            // (also: all warps done with MMA kt-1)
        if (kt + 1 < nktp)          // async copy overlaps the MMAs below
            issue_copy(kt + 1, (kt + 1) & 1);

        char* bb = smpool + (kt & 1) * STAGE_BYTES;
        bf* Ash = (bf*)(bb);
        bf* Asl = (bf*)(bb + ARR_BYTES);
        bf* Bsh = (bf*)(bb + 2 * ARR_BYTES);
        bf* Bsl = (bf*)(bb + 3 * ARR_BYTES);

        wm::fragment<wm::matrix_b, 16, 16, 16, bf, BLay> bfh[2], bfl[2];
#pragma unroll
        for (int n2 = 0; n2 < 2; n2++) {
            int n0 = wni * 32 + n2 * 16;
            int off = BT ? n0 : n0 * BLD;
            wm::load_matrix_sync(bfh[n2], &Bsh[off], BLD);
            wm::load_matrix_sync(bfl[n2], &Bsl[off], BLD);
        }
#pragma unroll
        for (int mt = 0; mt < 4; mt++) {
            wm::fragment<wm::matrix_a, 16, 16, 16, bf, ALay> afh, afl;
            int m0 = wmi * 64 + mt * 16;
            int off = AT ? m0 : m0 * ALD;
            wm::load_matrix_sync(afh, &Ash[off], ALD);
            wm::load_matrix_sync(afl, &Asl[off], ALD);
#pragma unroll
            for (int n2 = 0; n2 < 2; n2++) {
                wm::mma_sync(acc[mt][n2], afh, bfh[n2], acc[mt][n2]);
                wm::mma_sync(acc[mt][n2], afl, bfh[n2], acc[mt][n2]);
                wm::mma_sync(acc[mt][n2], afh, bfl[n2], acc[mt][n2]);
            }
        }
    }
    __syncthreads();   // protect pool before epilogue aliases it
}

// Epilogue: stage each frag through smem (aliases pool), then scalar writes.
// Exposes: row (0..127 tile-local), col (0..127 tile-local), v (float).
#define EPILOGUE(...)                                                     \
  { float* stg = (float*)(smpool) + (threadIdx.x >> 5) * 320;             \
    const int lane = threadIdx.x & 31;                                    \
    const int w = threadIdx.x >> 5, wm_ = w >> 2, wn_ = w & 3;            \
    for (int mt = 0; mt < 4; mt++)                                        \
      for (int n2 = 0; n2 < 2; n2++) {                                    \
        wm::store_matrix_sync(stg, acc[mt][n2], 20, wm::mem_row_major);   \
        __syncwarp();                                                     \
        _Pragma("unroll")                                                 \
        for (int e = 0; e < 8; e++) {                                     \
          int lr = 2 * e + (lane >> 4); int lc = lane & 15;               \
          int row = wm_ * 64 + mt * 16 + lr;                              \
          int col = wn_ * 32 + n2 * 16 + lc;                              \
          float v = stg[lr * 20 + lc];                                    \
          __VA_ARGS__                                                     \
        }                                                                 \
        __syncwarp();                                                     \
      } }

#define DECL_POOL __shared__ __align__(16) char smpool[POOL_BYTES]

__device__ __forceinline__ void split1(bf* Oh, bf* Ol, size_t idx, float v) {
    bf h = __float2bfloat16(v);
    Oh[idx] = h;
    Ol[idx] = __float2bfloat16(v - __bfloat162float(h));
}
__device__ __forceinline__ void split_store(bf* Oh, bf* Ol, size_t idx,
                                            float v0, float v1) {
    bf h0 = __float2bfloat16(v0), h1 = __float2bfloat16(v1);
    bf2 ph; ph.x = h0; ph.y = h1;
    bf2 pl; pl.x = __float2bfloat16(v0 - __bfloat162float(h0));
            pl.y = __float2bfloat16(v1 - __bfloat162float(h1));
    *(bf2*)(Oh + idx) = ph;
    *(bf2*)(Ol + idx) = pl;
}

// ---------------- conversion / scan ----------------------------------------
__global__ void conv_x_kernel(const float* __restrict__ x) {
    int i = blockIdx.x * 256 + threadIdx.x;       // over NROWS*DIM/4
    int r = i >> 7;
    int d = (i & 127) * 4;
    int tt = r >> 4, bb = r & 15;
    float4 v = *(const float4*)(x + (size_t)(bb * TLEN + tt) * DIM + d);
    size_t o = (size_t)r * DIM + d;
    split_store(g_Xh, g_Xl, o,     v.x, v.y);
    split_store(g_Xh, g_Xl, o + 2, v.z, v.w);
}

__global__ void conv_w_kernel(const float* __restrict__ Wq,
                              const float* __restrict__ Wk,
                              const float* __restrict__ Wv) {
    int i = blockIdx.x * 256 + threadIdx.x;       // over 3*DD2/4
    int z = i >> 16;
    int off = (i & 65535) * 4;
    const float* src = (z == 0) ? Wq : (z == 1) ? Wk : Wv;
    float4 v = *(const float4*)(src + off);
    size_t o = (size_t)z * DD2 + off;
    split_store(g_Wh, g_Wl, o,     v.x, v.y);
    split_store(g_Wh, g_Wl, o + 2, v.z, v.w);
}

__global__ void scan_kernel(const float* __restrict__ mem0) {
    int idx = blockIdx.x * 256 + threadIdx.x;     // over DD2 (scalar)
    float acc = mem0[idx];
    for (int g = 0; g < NG; g++) {
        size_t off = (size_t)g * DD2 + idx;
        float u = g_U[off];
        split1(g_Sh, g_Sl, off, acc);
        acc = fmaf(LRW, u, acc);
    }
}

// ---------------- GEMM kernels ---------------------------------------------
__global__ __launch_bounds__(256, 2) void gemm_qkv_kernel() {
    DECL_POOL;
    int mt0 = blockIdx.x, nt0 = blockIdx.y, z = blockIdx.z;
    const bf* Ah = g_Xh + (size_t)mt0 * 128 * DIM;
    const bf* Al = g_Xl + (size_t)mt0 * 128 * DIM;
    const bf* Bh = g_Wh + (size_t)z * DD2 + (size_t)nt0 * 128 * DIM;
    const bf* Bl = g_Wl + (size_t)z * DD2 + (size_t)nt0 * 128 * DIM;
    AccFrag acc[4][2];
    gemm_core<false, false>(smpool, Ah, Al, DIM, Bh, Bl, DIM, DIM / 16, acc);
    bf* Oh = (z == 0) ? g_Qh : (z == 1) ? g_Kh : g_Vh;
    bf* Ol = (z == 0) ? g_Ql : (z == 1) ? g_Kl : g_Vl;
    EPILOGUE(
        size_t idx = (size_t)(mt0 * 128 + row) * DIM + nt0 * 128 + col;
        split1(Oh, Ol, idx, v);
    )
}

// U_g[d,e] = sum_r V[r,d] K[r,e]   -- A = V read transposed, B = K read NN
__global__ __launch_bounds__(256, 2) void gemm_u_kernel() {
    DECL_POOL;
    int d0 = blockIdx.x * 128, e0 = blockIdx.y * 128, g = blockIdx.z;
    const bf* Ah = g_Vh + (size_t)(g * GROWS) * DIM + d0;
    const bf* Al = g_Vl + (size_t)(g * GROWS) * DIM + d0;
    const bf* Bh = g_Kh + (size_t)(g * GROWS) * DIM + e0;
    const bf* Bl = g_Kl + (size_t)(g * GROWS) * DIM + e0;
    AccFrag acc[4][2];
    gemm_core<true, true>(smpool, Ah, Al, DIM, Bh, Bl, DIM, GROWS / 16, acc);
    float* U = g_U + (size_t)g * DD2;
    EPILOGUE(
        U[(size_t)(d0 + row) * DIM + e0 + col] = v;
    )
}

__global__ __launch_bounds__(256, 2) void gemm_inter_kernel(float* __restrict__ out) {
    DECL_POOL;
    int mt0 = blockIdx.x, nt0 = blockIdx.y;
    int g = mt0 >> 1;
    const bf* Ah = g_Qh + (size_t)mt0 * 128 * DIM;
    const bf* Al = g_Ql + (size_t)mt0 * 128 * DIM;
    const bf* Bh = g_Sh + (size_t)g * DD2 + (size_t)nt0 * 128 * DIM;
    const bf* Bl = g_Sl + (size_t)g * DD2 + (size_t)nt0 * 128 * DIM;
    AccFrag acc[4][2];
    gemm_core<false, false>(smpool, Ah, Al, DIM, Bh, Bl, DIM, DIM / 16, acc);
    EPILOGUE(
        int r = mt0 * 128 + row;
        int tt = r >> 4; int bb = r & 15;
        out[(size_t)(bb * TLEN + tt) * DIM + nt0 * 128 + col] = v;
    )
}

__global__ __launch_bounds__(256, 2) void gemm_score_kernel() {
    DECL_POOL;
    int id = blockIdx.x;                 // 0:(0,0) 1:(1,0) 2:(1,1)
    int ti = (id == 0) ? 0 : 1;
    int tj = (id == 2) ? 1 : 0;
    int g = blockIdx.y;
    const bf* Ah = g_Qh + (size_t)(g * GROWS + ti * 128) * DIM;
    const bf* Al = g_Ql + (size_t)(g * GROWS + ti * 128) * DIM;
    const bf* Bh = g_Kh + (size_t)(g * GROWS + tj * 128) * DIM;
    const bf* Bl = g_Kl + (size_t)(g * GROWS + tj * 128) * DIM;
    AccFrag acc[4][2];
    gemm_core<false, false>(smpool, Ah, Al, DIM, Bh, Bl, DIM, DIM / 16, acc);
    bf* Sch = g_Sch + (size_t)g * GR2;
    bf* Scl = g_Scl + (size_t)g * GR2;
    EPILOGUE(
        int rr = ti * 128 + row;
        int ss = tj * 128 + col;
        float m = ((ss >> 4) <= (rr >> 4)) ? LRW * v : 0.0f;
        split1(Sch, Scl, (size_t)rr * GROWS + ss, m);
    )
}

// out[r,d] += sum_s Sc[r,s] V[s,d]  -- B = V read NN
__global__ __launch_bounds__(256, 2) void gemm_av_kernel(float* __restrict__ out) {
    DECL_POOL;
    int ti = blockIdx.x;                 // 0..1 row tile within group
    int nt0 = blockIdx.y;                // 0..3
    int g = blockIdx.z;
    const bf* Ah = g_Sch + (size_t)g * GR2 + (size_t)ti * 128 * GROWS;
    const bf* Al = g_Scl + (size_t)g * GR2 + (size_t)ti * 128 * GROWS;
    const bf* Bh = g_Vh + (size_t)(g * GROWS) * DIM + nt0 * 128;
    const bf* Bl = g_Vl + (size_t)(g * GROWS) * DIM + nt0 * 128;
    AccFrag acc[4][2];
    gemm_core<false, true>(smpool, Ah, Al, GROWS, Bh, Bl, DIM, 8 * (ti + 1), acc);
    EPILOGUE(
        int r = g * GROWS + ti * 128 + row;
        int tt = r >> 4; int bb = r & 15;
        size_t idx = (size_t)(bb * TLEN + tt) * DIM + nt0 * 128 + col;
        out[idx] += v;
    )
}

// ---------------------------------------------------------------------------
extern "C" void kernel_launch(void* const* d_in, const int* in_sizes, int n_in,
                              void* d_out, int out_size) {
    (void)in_sizes; (void)n_in; (void)out_size;
    const float* x  = (const float*)d_in[0];
    const float* Wq = (const float*)d_in[1];
    const float* Wk = (const float*)d_in[2];
    const float* Wv = (const float*)d_in[3];
    const float* m0 = (const float*)d_in[4];
    float* out = (float*)d_out;

    conv_x_kernel<<<32768, 256>>>(x);
    conv_w_kernel<<<768, 256>>>(Wq, Wk, Wv);
    gemm_qkv_kernel<<<dim3(512, 4, 3), 256>>>();
    gemm_u_kernel<<<dim3(4, 4, 256), 256>>>();
    scan_kernel<<<1024, 256>>>(m0);
    gemm_score_kernel<<<dim3(3, 256), 256>>>();
    gemm_inter_kernel<<<dim3(512, 4), 256>>>(out);
    gemm_av_kernel<<<dim3(2, 4, 256), 256>>>(out);
}

// round 14
// speedup vs baseline: 2.7066x; 1.4390x over previous
#include <cuda_runtime.h>
#include <cuda_fp16.h>
#include <cuda_pipeline.h>
#include <mma.h>
#include <cstdint>
#include <type_traits>

typedef __half hf;
namespace wm = nvcuda::wmma;
using AccFrag = wm::fragment<wm::accumulator, 16, 16, 16, float>;

#define BATCH 16
#define TLEN  4096
#define DIM   512
#define NROWS 65536              // time-major rows r = t*16 + b
#define GROWS 256                // rows per group (16 t-steps x 16 batch)
#define NG    256
#define DD2   (DIM*DIM)          // 262144
#define GR2   (GROWS*GROWS)
#define LRW   0.01f

// ---------------- device scratch ----------------
// A-side operands need exact hi/lo fp16 pairs; B-side operands need hi only.
__device__ __align__(256) hf g_Xh[(size_t)NROWS*DIM];
__device__ __align__(256) hf g_Xl[(size_t)NROWS*DIM];
__device__ __align__(256) hf g_Wh[3*DD2];                 // B only
__device__ __align__(256) hf g_Qh[(size_t)NROWS*DIM];
__device__ __align__(256) hf g_Ql[(size_t)NROWS*DIM];
__device__ __align__(256) hf g_Kh[(size_t)NROWS*DIM];     // B only
__device__ __align__(256) hf g_Vh[(size_t)NROWS*DIM];     // A (u) + B (av)
__device__ __align__(256) hf g_Vl[(size_t)NROWS*DIM];
__device__ __align__(256) float g_U[(size_t)NG*DD2];
__device__ __align__(256) hf g_Sh[(size_t)NG*DD2];        // B only
__device__ __align__(256) hf g_Sch[(size_t)NG*GR2];
__device__ __align__(256) hf g_Scl[(size_t)NG*GR2];

// 2 stages x 3 arrays x 6KB = 36KB static; epilogue staging aliases stage 0
#define POOL_BYTES 36864
#define STAGE_BYTES 18432
#define ARR_BYTES 6144

// ---------------------------------------------------------------------------
// 128x128 GEMM core, fp16 exact-A-split 2-product (Ah*Bh + Al*Bh = A*Bh),
// BK=16, double-buffered smem with cp.async; 1 barrier per chunk.
//   AT=false: A stored [m][k] k-contig (row_major frag)
//   AT=true : A stored [k][m] m-contig (col_major frag)
//   BT=false: B stored [n][k] k-contig (col_major frag)  -- NT
//   BT=true : B stored [k][n] n-contig (row_major frag)  -- NN
// 256 threads, 8 warps 2x4, warp tile 64x32 = 4x2 fragments.
// ---------------------------------------------------------------------------
template <bool AT, bool BT>
__device__ __forceinline__ void gemm_core(char* smpool,
    const hf* __restrict__ Ah, const hf* __restrict__ Al, size_t lda,
    const hf* __restrict__ Bh, size_t ldb,
    int nktp, AccFrag acc[4][2])
{
    constexpr int ALD = AT ? 136 : 24;   // AT tile: 16x136, else 128x24
    constexpr int BLD = BT ? 136 : 24;

    const int tid = threadIdx.x;
    const int w   = tid >> 5;
    const int wmi = w >> 2, wni = w & 3;

    // loader: each thread copies 1x16B per array per chunk
    const int ar  = AT ? (tid >> 4) : (tid >> 1);
    const int acb = (AT ? (tid & 15) : (tid & 1)) * 8;
    const int br  = BT ? (tid >> 4) : (tid >> 1);
    const int bcb = (BT ? (tid & 15) : (tid & 1)) * 8;
    const int aso = (ar * ALD + acb) * 2;   // byte offsets (16B aligned)
    const int bso = (br * BLD + bcb) * 2;

    auto agof = [&](int kt) -> size_t {
        return AT ? (size_t)(kt * 16 + ar) * lda + acb
                  : (size_t)ar * lda + kt * 16 + acb;
    };
    auto bgof = [&](int kt) -> size_t {
        return BT ? (size_t)(kt * 16 + br) * ldb + bcb
                  : (size_t)br * ldb + kt * 16 + bcb;
    };

    auto issue_copy = [&](int kt, int buf) {
        char* bb = smpool + buf * STAGE_BYTES;
        __pipeline_memcpy_async(bb + aso,                 Ah + agof(kt), 16);
        __pipeline_memcpy_async(bb + ARR_BYTES + aso,     Al + agof(kt), 16);
        __pipeline_memcpy_async(bb + 2 * ARR_BYTES + bso, Bh + bgof(kt), 16);
        __pipeline_commit();
    };

#pragma unroll
    for (int mt = 0; mt < 4; mt++)
#pragma unroll
        for (int n2 = 0; n2 < 2; n2++)
            wm::fill_fragment(acc[mt][n2], 0.0f);

    using ALay = typename std::conditional<AT, wm::col_major, wm::row_major>::type;
    using BLay = typename std::conditional<BT, wm::row_major, wm::col_major>::type;

    issue_copy(0, 0);

    for (int kt = 0; kt < nktp; ++kt) {
        __pipeline_wait_prior(0);   // chunk kt's copy complete
        __syncthreads();            // (also: all warps done with MMA kt-1)
        if (kt + 1 < nktp)          // async copy overlaps the MMAs below
            issue_copy(kt + 1, (kt + 1) & 1);

        char* bb = smpool + (kt & 1) * STAGE_BYTES;
        hf* Ash = (hf*)(bb);
        hf* Asl = (hf*)(bb + ARR_BYTES);
        hf* Bsh = (hf*)(bb + 2 * ARR_BYTES);

        wm::fragment<wm::matrix_b, 16, 16, 16, hf, BLay> bfh[2];
#pragma unroll
        for (int n2 = 0; n2 < 2; n2++) {
            int n0 = wni * 32 + n2 * 16;
            int off = BT ? n0 : n0 * BLD;
            wm::load_matrix_sync(bfh[n2], &Bsh[off], BLD);
        }
#pragma unroll
        for (int mt = 0; mt < 4; mt++) {
            wm::fragment<wm::matrix_a, 16, 16, 16, hf, ALay> afh, afl;
            int m0 = wmi * 64 + mt * 16;
            int off = AT ? m0 : m0 * ALD;
            wm::load_matrix_sync(afh, &Ash[off], ALD);
            wm::load_matrix_sync(afl, &Asl[off], ALD);
#pragma unroll
            for (int n2 = 0; n2 < 2; n2++) {
                wm::mma_sync(acc[mt][n2], afh, bfh[n2], acc[mt][n2]);
                wm::mma_sync(acc[mt][n2], afl, bfh[n2], acc[mt][n2]);
            }
        }
    }
    __syncthreads();   // protect pool before epilogue aliases it
}

// Epilogue: stage each frag through smem (aliases pool), then scalar writes.
// Exposes: row (0..127 tile-local), col (0..127 tile-local), v (float).
#define EPILOGUE(...)                                                     \
  { float* stg = (float*)(smpool) + (threadIdx.x >> 5) * 320;             \
    const int lane = threadIdx.x & 31;                                    \
    const int w = threadIdx.x >> 5, wm_ = w >> 2, wn_ = w & 3;            \
    for (int mt = 0; mt < 4; mt++)                                        \
      for (int n2 = 0; n2 < 2; n2++) {                                    \
        wm::store_matrix_sync(stg, acc[mt][n2], 20, wm::mem_row_major);   \
        __syncwarp();                                                     \
        _Pragma("unroll")                                                 \
        for (int e = 0; e < 8; e++) {                                     \
          int lr = 2 * e + (lane >> 4); int lc = lane & 15;               \
          int row = wm_ * 64 + mt * 16 + lr;                              \
          int col = wn_ * 32 + n2 * 16 + lc;                              \
          float v = stg[lr * 20 + lc];                                    \
          __VA_ARGS__                                                     \
        }                                                                 \
        __syncwarp();                                                     \
      } }

#define DECL_POOL __shared__ __align__(16) char smpool[POOL_BYTES]

__device__ __forceinline__ void split1(hf* Oh, hf* Ol, size_t idx, float v) {
    hf h = __float2half_rn(v);
    Oh[idx] = h;
    Ol[idx] = __float2half_rn(v - __half2float(h));
}

// ---------------- conversion / scan ----------------------------------------
__global__ void conv_x_kernel(const float* __restrict__ x) {
    int i = blockIdx.x * 256 + threadIdx.x;       // over NROWS*DIM/4
    int r = i >> 7;
    int d = (i & 127) * 4;
    int tt = r >> 4, bb = r & 15;
    float4 v = *(const float4*)(x + (size_t)(bb * TLEN + tt) * DIM + d);
    size_t o = (size_t)r * DIM + d;
    split1(g_Xh, g_Xl, o,     v.x);
    split1(g_Xh, g_Xl, o + 1, v.y);
    split1(g_Xh, g_Xl, o + 2, v.z);
    split1(g_Xh, g_Xl, o + 3, v.w);
}

__global__ void conv_w_kernel(const float* __restrict__ Wq,
                              const float* __restrict__ Wk,
                              const float* __restrict__ Wv) {
    int i = blockIdx.x * 256 + threadIdx.x;       // over 3*DD2/4
    int z = i >> 16;
    int off = (i & 65535) * 4;
    const float* src = (z == 0) ? Wq : (z == 1) ? Wk : Wv;
    float4 v = *(const float4*)(src + off);
    size_t o = (size_t)z * DD2 + off;
    g_Wh[o]     = __float2half_rn(v.x);
    g_Wh[o + 1] = __float2half_rn(v.y);
    g_Wh[o + 2] = __float2half_rn(v.z);
    g_Wh[o + 3] = __float2half_rn(v.w);
}

__global__ void scan_kernel(const float* __restrict__ mem0) {
    int idx = blockIdx.x * 256 + threadIdx.x;     // over DD2 (scalar)
    float acc = mem0[idx];
    for (int g = 0; g < NG; g++) {
        size_t off = (size_t)g * DD2 + idx;
        float u = g_U[off];
        g_Sh[off] = __float2half_rn(acc);
        acc = fmaf(LRW, u, acc);
    }
}

// ---------------- GEMM kernels ---------------------------------------------
__global__ __launch_bounds__(256, 2) void gemm_qkv_kernel() {
    DECL_POOL;
    int mt0 = blockIdx.x, nt0 = blockIdx.y, z = blockIdx.z;
    const hf* Ah = g_Xh + (size_t)mt0 * 128 * DIM;
    const hf* Al = g_Xl + (size_t)mt0 * 128 * DIM;
    const hf* Bh = g_Wh + (size_t)z * DD2 + (size_t)nt0 * 128 * DIM;
    AccFrag acc[4][2];
    gemm_core<false, false>(smpool, Ah, Al, DIM, Bh, DIM, DIM / 16, acc);
    if (z == 1) {          // K: B-side only, single fp16
        EPILOGUE(
            g_Kh[(size_t)(mt0 * 128 + row) * DIM + nt0 * 128 + col] =
                __float2half_rn(v);
        )
    } else {               // Q, V: A-side, exact hi/lo split
        hf* Oh = (z == 0) ? g_Qh : g_Vh;
        hf* Ol = (z == 0) ? g_Ql : g_Vl;
        EPILOGUE(
            size_t idx = (size_t)(mt0 * 128 + row) * DIM + nt0 * 128 + col;
            split1(Oh, Ol, idx, v);
        )
    }
}

// U_g[d,e] = sum_r V[r,d] K[r,e]   -- A = V read transposed, B = K read NN
__global__ __launch_bounds__(256, 2) void gemm_u_kernel() {
    DECL_POOL;
    int d0 = blockIdx.x * 128, e0 = blockIdx.y * 128, g = blockIdx.z;
    const hf* Ah = g_Vh + (size_t)(g * GROWS) * DIM + d0;
    const hf* Al = g_Vl + (size_t)(g * GROWS) * DIM + d0;
    const hf* Bh = g_Kh + (size_t)(g * GROWS) * DIM + e0;
    AccFrag acc[4][2];
    gemm_core<true, true>(smpool, Ah, Al, DIM, Bh, DIM, GROWS / 16, acc);
    float* U = g_U + (size_t)g * DD2;
    EPILOGUE(
        U[(size_t)(d0 + row) * DIM + e0 + col] = v;
    )
}

__global__ __launch_bounds__(256, 2) void gemm_inter_kernel(float* __restrict__ out) {
    DECL_POOL;
    int mt0 = blockIdx.x, nt0 = blockIdx.y;
    int g = mt0 >> 1;
    const hf* Ah = g_Qh + (size_t)mt0 * 128 * DIM;
    const hf* Al = g_Ql + (size_t)mt0 * 128 * DIM;
    const hf* Bh = g_Sh + (size_t)g * DD2 + (size_t)nt0 * 128 * DIM;
    AccFrag acc[4][2];
    gemm_core<false, false>(smpool, Ah, Al, DIM, Bh, DIM, DIM / 16, acc);
    EPILOGUE(
        int r = mt0 * 128 + row;
        int tt = r >> 4; int bb = r & 15;
        out[(size_t)(bb * TLEN + tt) * DIM + nt0 * 128 + col] = v;
    )
}

__global__ __launch_bounds__(256, 2) void gemm_score_kernel() {
    DECL_POOL;
    int id = blockIdx.x;                 // 0:(0,0) 1:(1,0) 2:(1,1)
    int ti = (id == 0) ? 0 : 1;
    int tj = (id == 2) ? 1 : 0;
    int g = blockIdx.y;
    const hf* Ah = g_Qh + (size_t)(g * GROWS + ti * 128) * DIM;
    const hf* Al = g_Ql + (size_t)(g * GROWS + ti * 128) * DIM;
    const hf* Bh = g_Kh + (size_t)(g * GROWS + tj * 128) * DIM;
    AccFrag acc[4][2];
    gemm_core<false, false>(smpool, Ah, Al, DIM, Bh, DIM, DIM / 16, acc);
    hf* Sch = g_Sch + (size_t)g * GR2;
    hf* Scl = g_Scl + (size_t)g * GR2;
    EPILOGUE(
        int rr = ti * 128 + row;
        int ss = tj * 128 + col;
        float m = ((ss >> 4) <= (rr >> 4)) ? LRW * v : 0.0f;
        split1(Sch, Scl, (size_t)rr * GROWS + ss, m);
    )
}

// out[r,d] += sum_s Sc[r,s] V[s,d]  -- B = V read NN
__global__ __launch_bounds__(256, 2) void gemm_av_kernel(float* __restrict__ out) {
    DECL_POOL;
    int ti = blockIdx.x;                 // 0..1 row tile within group
    int nt0 = blockIdx.y;                // 0..3
    int g = blockIdx.z;
    const hf* Ah = g_Sch + (size_t)g * GR2 + (size_t)ti * 128 * GROWS;
    const hf* Al = g_Scl + (size_t)g * GR2 + (size_t)ti * 128 * GROWS;
    const hf* Bh = g_Vh + (size_t)(g * GROWS) * DIM + nt0 * 128;
    AccFrag acc[4][2];
    gemm_core<false, true>(smpool, Ah, Al, GROWS, Bh, DIM, 8 * (ti + 1), acc);
    EPILOGUE(
        int r = g * GROWS + ti * 128 + row;
        int tt = r >> 4; int bb = r & 15;
        size_t idx = (size_t)(bb * TLEN + tt) * DIM + nt0 * 128 + col;
        out[idx] += v;
    )
}

// ---------------------------------------------------------------------------
extern "C" void kernel_launch(void* const* d_in, const int* in_sizes, int n_in,
                              void* d_out, int out_size) {
    (void)in_sizes; (void)n_in; (void)out_size;
    const float* x  = (const float*)d_in[0];
    const float* Wq = (const float*)d_in[1];
    const float* Wk = (const float*)d_in[2];
    const float* Wv = (const float*)d_in[3];
    const float* m0 = (const float*)d_in[4];
    float* out = (float*)d_out;

    conv_x_kernel<<<32768, 256>>>(x);
    conv_w_kernel<<<768, 256>>>(Wq, Wk, Wv);
    gemm_qkv_kernel<<<dim3(512, 4, 3), 256>>>();
    gemm_u_kernel<<<dim3(4, 4, 256), 256>>>();
    scan_kernel<<<1024, 256>>>(m0);
    gemm_score_kernel<<<dim3(3, 256), 256>>>();
    gemm_inter_kernel<<<dim3(512, 4), 256>>>(out);
    gemm_av_kernel<<<dim3(2, 4, 256), 256>>>(out);
}

// round 15
// speedup vs baseline: 3.1307x; 1.1567x over previous
#include <cuda_runtime.h>
#include <cuda_fp16.h>
#include <cuda_pipeline.h>
#include <mma.h>
#include <cstdint>
#include <type_traits>

typedef __half hf;
namespace wm = nvcuda::wmma;
using AccFrag = wm::fragment<wm::accumulator, 16, 16, 16, float>;

#define BATCH 16
#define TLEN  4096
#define DIM   512
#define NROWS 65536              // time-major rows r = t*16 + b
#define GROWS 256                // rows per group (16 t-steps x 16 batch)
#define NG    256
#define DD2   (DIM*DIM)          // 262144
#define GR2   (GROWS*GROWS)
#define LRW   0.01f

// ---------------- device scratch ----------------
// A-side operands that keep exact hi/lo fp16 pairs: Q, V, Sc. X and all
// B-side operands (W, K, S) are rounded once.
__device__ __align__(256) hf g_Xh[(size_t)NROWS*DIM];
__device__ __align__(256) hf g_Wh[3*DD2];
__device__ __align__(256) hf g_Qh[(size_t)NROWS*DIM];
__device__ __align__(256) hf g_Ql[(size_t)NROWS*DIM];
__device__ __align__(256) hf g_Kh[(size_t)NROWS*DIM];
__device__ __align__(256) hf g_Vh[(size_t)NROWS*DIM];
__device__ __align__(256) hf g_Vl[(size_t)NROWS*DIM];
__device__ __align__(256) float g_U[(size_t)NG*DD2];
__device__ __align__(256) hf g_Sh[(size_t)NG*DD2];
__device__ __align__(256) hf g_Sch[(size_t)NG*GR2];
__device__ __align__(256) hf g_Scl[(size_t)NG*GR2];

// 2 stages x 3 arrays x 6KB = 36KB static; epilogue staging aliases stage 0
#define POOL_BYTES 36864
#define STAGE_BYTES 18432
#define ARR_BYTES 6144

// ---------------------------------------------------------------------------
// 128x128 GEMM core, fp16, BK=16, double-buffered smem with cp.async.
//   SPLITA=true : A given as exact hi/lo pair -> 2 products (A*Bh exact in A)
//   SPLITA=false: A rounded once -> 1 product
//   AT=false: A stored [m][k] k-contig (row_major frag)
//   AT=true : A stored [k][m] m-contig (col_major frag)
//   BT=false: B stored [n][k] k-contig (col_major frag)  -- NT
//   BT=true : B stored [k][n] n-contig (row_major frag)  -- NN
// 256 threads, 8 warps 2x4, warp tile 64x32 = 4x2 fragments.
// ---------------------------------------------------------------------------
template <bool AT, bool BT, bool SPLITA>
__device__ __forceinline__ void gemm_core(char* smpool,
    const hf* __restrict__ Ah, const hf* __restrict__ Al, size_t lda,
    const hf* __restrict__ Bh, size_t ldb,
    int nktp, AccFrag acc[4][2])
{
    constexpr int ALD = AT ? 136 : 24;   // AT tile: 16x136, else 128x24
    constexpr int BLD = BT ? 136 : 24;

    const int tid = threadIdx.x;
    const int w   = tid >> 5;
    const int wmi = w >> 2, wni = w & 3;

    // loader: each thread copies 1x16B per array per chunk
    const int ar  = AT ? (tid >> 4) : (tid >> 1);
    const int acb = (AT ? (tid & 15) : (tid & 1)) * 8;
    const int br  = BT ? (tid >> 4) : (tid >> 1);
    const int bcb = (BT ? (tid & 15) : (tid & 1)) * 8;
    const int aso = (ar * ALD + acb) * 2;   // byte offsets (16B aligned)
    const int bso = (br * BLD + bcb) * 2;

    auto agof = [&](int kt) -> size_t {
        return AT ? (size_t)(kt * 16 + ar) * lda + acb
                  : (size_t)ar * lda + kt * 16 + acb;
    };
    auto bgof = [&](int kt) -> size_t {
        return BT ? (size_t)(kt * 16 + br) * ldb + bcb
                  : (size_t)br * ldb + kt * 16 + bcb;
    };

    auto issue_copy = [&](int kt, int buf) {
        char* bb = smpool + buf * STAGE_BYTES;
        __pipeline_memcpy_async(bb + aso,                 Ah + agof(kt), 16);
        if (SPLITA)
            __pipeline_memcpy_async(bb + ARR_BYTES + aso, Al + agof(kt), 16);
        __pipeline_memcpy_async(bb + 2 * ARR_BYTES + bso, Bh + bgof(kt), 16);
        __pipeline_commit();
    };

#pragma unroll
    for (int mt = 0; mt < 4; mt++)
#pragma unroll
        for (int n2 = 0; n2 < 2; n2++)
            wm::fill_fragment(acc[mt][n2], 0.0f);

    using ALay = typename std::conditional<AT, wm::col_major, wm::row_major>::type;
    using BLay = typename std::conditional<BT, wm::row_major, wm::col_major>::type;

    issue_copy(0, 0);

    for (int kt = 0; kt < nktp; ++kt) {
        __pipeline_wait_prior(0);   // chunk kt's copy complete
        __syncthreads();            // (also: all warps done with MMA kt-1)
        if (kt + 1 < nktp)          // async copy overlaps the MMAs below
            issue_copy(kt + 1, (kt + 1) & 1);

        char* bb = smpool + (kt & 1) * STAGE_BYTES;
        hf* Ash = (hf*)(bb);
        hf* Asl = (hf*)(bb + ARR_BYTES);
        hf* Bsh = (hf*)(bb + 2 * ARR_BYTES);

        wm::fragment<wm::matrix_b, 16, 16, 16, hf, BLay> bfh[2];
#pragma unroll
        for (int n2 = 0; n2 < 2; n2++) {
            int n0 = wni * 32 + n2 * 16;
            int off = BT ? n0 : n0 * BLD;
            wm::load_matrix_sync(bfh[n2], &Bsh[off], BLD);
        }
#pragma unroll
        for (int mt = 0; mt < 4; mt++) {
            wm::fragment<wm::matrix_a, 16, 16, 16, hf, ALay> afh, afl;
            int m0 = wmi * 64 + mt * 16;
            int off = AT ? m0 : m0 * ALD;
            wm::load_matrix_sync(afh, &Ash[off], ALD);
            if (SPLITA) wm::load_matrix_sync(afl, &Asl[off], ALD);
#pragma unroll
            for (int n2 = 0; n2 < 2; n2++) {
                wm::mma_sync(acc[mt][n2], afh, bfh[n2], acc[mt][n2]);
                if (SPLITA)
                    wm::mma_sync(acc[mt][n2], afl, bfh[n2], acc[mt][n2]);
            }
        }
    }
    __syncthreads();   // protect pool before epilogue aliases it
}

// Epilogue: stage each frag through smem (aliases pool), then scalar writes.
// Exposes: row (0..127 tile-local), col (0..127 tile-local), v (float).
#define EPILOGUE(...)                                                     \
  { float* stg = (float*)(smpool) + (threadIdx.x >> 5) * 320;             \
    const int lane = threadIdx.x & 31;                                    \
    const int w = threadIdx.x >> 5, wm_ = w >> 2, wn_ = w & 3;            \
    for (int mt = 0; mt < 4; mt++)                                        \
      for (int n2 = 0; n2 < 2; n2++) {                                    \
        wm::store_matrix_sync(stg, acc[mt][n2], 20, wm::mem_row_major);   \
        __syncwarp();                                                     \
        _Pragma("unroll")                                                 \
        for (int e = 0; e < 8; e++) {                                     \
          int lr = 2 * e + (lane >> 4); int lc = lane & 15;               \
          int row = wm_ * 64 + mt * 16 + lr;                              \
          int col = wn_ * 32 + n2 * 16 + lc;                              \
          float v = stg[lr * 20 + lc];                                    \
          __VA_ARGS__                                                     \
        }                                                                 \
        __syncwarp();                                                     \
      } }

#define DECL_POOL __shared__ __align__(16) char smpool[POOL_BYTES]

__device__ __forceinline__ void split1(hf* Oh, hf* Ol, size_t idx, float v) {
    hf h = __float2half_rn(v);
    Oh[idx] = h;
    Ol[idx] = __float2half_rn(v - __half2float(h));
}

// ---------------- conversion / scan ----------------------------------------
__global__ void conv_x_kernel(const float* __restrict__ x) {
    int i = blockIdx.x * 256 + threadIdx.x;       // over NROWS*DIM/4
    int r = i >> 7;
    int d = (i & 127) * 4;
    int tt = r >> 4, bb = r & 15;
    float4 v = *(const float4*)(x + (size_t)(bb * TLEN + tt) * DIM + d);
    size_t o = (size_t)r * DIM + d;
    g_Xh[o]     = __float2half_rn(v.x);
    g_Xh[o + 1] = __float2half_rn(v.y);
    g_Xh[o + 2] = __float2half_rn(v.z);
    g_Xh[o + 3] = __float2half_rn(v.w);
}

__global__ void conv_w_kernel(const float* __restrict__ Wq,
                              const float* __restrict__ Wk,
                              const float* __restrict__ Wv) {
    int i = blockIdx.x * 256 + threadIdx.x;       // over 3*DD2/4
    int z = i >> 16;
    int off = (i & 65535) * 4;
    const float* src = (z == 0) ? Wq : (z == 1) ? Wk : Wv;
    float4 v = *(const float4*)(src + off);
    size_t o = (size_t)z * DD2 + off;
    g_Wh[o]     = __float2half_rn(v.x);
    g_Wh[o + 1] = __float2half_rn(v.y);
    g_Wh[o + 2] = __float2half_rn(v.z);
    g_Wh[o + 3] = __float2half_rn(v.w);
}

__global__ void scan_kernel(const float* __restrict__ mem0) {
    int idx = blockIdx.x * 256 + threadIdx.x;     // over DD2 (scalar)
    float acc = mem0[idx];
    for (int g = 0; g < NG; g++) {
        size_t off = (size_t)g * DD2 + idx;
        float u = g_U[off];
        g_Sh[off] = __float2half_rn(acc);
        acc = fmaf(LRW, u, acc);
    }
}

// ---------------- GEMM kernels ---------------------------------------------
// QKV: single product (X rounded once) — halves the dominant GEMM stage.
__global__ __launch_bounds__(256, 2) void gemm_qkv_kernel() {
    DECL_POOL;
    int mt0 = blockIdx.x, nt0 = blockIdx.y, z = blockIdx.z;
    const hf* Ah = g_Xh + (size_t)mt0 * 128 * DIM;
    const hf* Bh = g_Wh + (size_t)z * DD2 + (size_t)nt0 * 128 * DIM;
    AccFrag acc[4][2];
    gemm_core<false, false, false>(smpool, Ah, nullptr, DIM, Bh, DIM,
                                   DIM / 16, acc);
    if (z == 1) {          // K: B-side only, single fp16
        EPILOGUE(
            g_Kh[(size_t)(mt0 * 128 + row) * DIM + nt0 * 128 + col] =
                __float2half_rn(v);
        )
    } else {               // Q, V: A-side downstream, exact hi/lo split
        hf* Oh = (z == 0) ? g_Qh : g_Vh;
        hf* Ol = (z == 0) ? g_Ql : g_Vl;
        EPILOGUE(
            size_t idx = (size_t)(mt0 * 128 + row) * DIM + nt0 * 128 + col;
            split1(Oh, Ol, idx, v);
        )
    }
}

// U_g[d,e] = sum_r V[r,d] K[r,e]   -- A = V read transposed, B = K read NN
__global__ __launch_bounds__(256, 2) void gemm_u_kernel() {
    DECL_POOL;
    int d0 = blockIdx.x * 128, e0 = blockIdx.y * 128, g = blockIdx.z;
    const hf* Ah = g_Vh + (size_t)(g * GROWS) * DIM + d0;
    const hf* Al = g_Vl + (size_t)(g * GROWS) * DIM + d0;
    const hf* Bh = g_Kh + (size_t)(g * GROWS) * DIM + e0;
    AccFrag acc[4][2];
    gemm_core<true, true, true>(smpool, Ah, Al, DIM, Bh, DIM, GROWS / 16, acc);
    float* U = g_U + (size_t)g * DD2;
    EPILOGUE(
        U[(size_t)(d0 + row) * DIM + e0 + col] = v;
    )
}

__global__ __launch_bounds__(256, 2) void gemm_inter_kernel(float* __restrict__ out) {
    DECL_POOL;
    int mt0 = blockIdx.x, nt0 = blockIdx.y;
    int g = mt0 >> 1;
    const hf* Ah = g_Qh + (size_t)mt0 * 128 * DIM;
    const hf* Al = g_Ql + (size_t)mt0 * 128 * DIM;
    const hf* Bh = g_Sh + (size_t)g * DD2 + (size_t)nt0 * 128 * DIM;
    AccFrag acc[4][2];
    gemm_core<false, false, true>(smpool, Ah, Al, DIM, Bh, DIM, DIM / 16, acc);
    EPILOGUE(
        int r = mt0 * 128 + row;
        int tt = r >> 4; int bb = r & 15;
        out[(size_t)(bb * TLEN + tt) * DIM + nt0 * 128 + col] = v;
    )
}

__global__ __launch_bounds__(256, 2) void gemm_score_kernel() {
    DECL_POOL;
    int id = blockIdx.x;                 // 0:(0,0) 1:(1,0) 2:(1,1)
    int ti = (id == 0) ? 0 : 1;
    int tj = (id == 2) ? 1 : 0;
    int g = blockIdx.y;
    const hf* Ah = g_Qh + (size_t)(g * GROWS + ti * 128) * DIM;
    const hf* Al = g_Ql + (size_t)(g * GROWS + ti * 128) * DIM;
    const hf* Bh = g_Kh + (size_t)(g * GROWS + tj * 128) * DIM;
    AccFrag acc[4][2];
    gemm_core<false, false, true>(smpool, Ah, Al, DIM, Bh, DIM, DIM / 16, acc);
    hf* Sch = g_Sch + (size_t)g * GR2;
    hf* Scl = g_Scl + (size_t)g * GR2;
    EPILOGUE(
        int rr = ti * 128 + row;
        int ss = tj * 128 + col;
        float m = ((ss >> 4) <= (rr >> 4)) ? LRW * v : 0.0f;
        split1(Sch, Scl, (size_t)rr * GROWS + ss, m);
    )
}

// out[r,d] += sum_s Sc[r,s] V[s,d]  -- B = V read NN
__global__ __launch_bounds__(256, 2) void gemm_av_kernel(float* __restrict__ out) {
    DECL_POOL;
    int ti = blockIdx.x;                 // 0..1 row tile within group
    int nt0 = blockIdx.y;                // 0..3
    int g = blockIdx.z;
    const hf* Ah = g_Sch + (size_t)g * GR2 + (size_t)ti * 128 * GROWS;
    const hf* Al = g_Scl + (size_t)g * GR2 + (size_t)ti * 128 * GROWS;
    const hf* Bh = g_Vh + (size_t)(g * GROWS) * DIM + nt0 * 128;
    AccFrag acc[4][2];
    gemm_core<false, true, true>(smpool, Ah, Al, GROWS, Bh, DIM,
                                 8 * (ti + 1), acc);
    EPILOGUE(
        int r = g * GROWS + ti * 128 + row;
        int tt = r >> 4; int bb = r & 15;
        size_t idx = (size_t)(bb * TLEN + tt) * DIM + nt0 * 128 + col;
        out[idx] += v;
    )
}

// ---------------------------------------------------------------------------
extern "C" void kernel_launch(void* const* d_in, const int* in_sizes, int n_in,
                              void* d_out, int out_size) {
    (void)in_sizes; (void)n_in; (void)out_size;
    const float* x  = (const float*)d_in[0];
    const float* Wq = (const float*)d_in[1];
    const float* Wk = (const float*)d_in[2];
    const float* Wv = (const float*)d_in[3];
    const float* m0 = (const float*)d_in[4];
    float* out = (float*)d_out;

    conv_x_kernel<<<32768, 256>>>(x);
    conv_w_kernel<<<768, 256>>>(Wq, Wk, Wv);
    gemm_qkv_kernel<<<dim3(512, 4, 3), 256>>>();
    gemm_u_kernel<<<dim3(4, 4, 256), 256>>>();
    scan_kernel<<<1024, 256>>>(m0);
    gemm_score_kernel<<<dim3(3, 256), 256>>>();
    gemm_inter_kernel<<<dim3(512, 4), 256>>>(out);
    gemm_av_kernel<<<dim3(2, 4, 256), 256>>>(out);
}

// round 16
// speedup vs baseline: 3.5557x; 1.1358x over previous
#include <cuda_runtime.h>
#include <cuda_fp16.h>
#include <cuda_pipeline.h>
#include <mma.h>
#include <cstdint>
#include <type_traits>

typedef __half hf;
namespace wm = nvcuda::wmma;
using AccFrag = wm::fragment<wm::accumulator, 16, 16, 16, float>;

#define BATCH 16
#define TLEN  4096
#define DIM   512
#define NROWS 65536              // time-major rows r = t*16 + b
#define GROWS 256                // rows per group (16 t-steps x 16 batch)
#define NG    256
#define DD2   (DIM*DIM)          // 262144
#define GR2   (GROWS*GROWS)
#define LRW   0.01f

// ---------------- device scratch ----------------
// Exact hi/lo fp16 pairs kept for: Q (score), V (u), Sc (av).
// Rounded once: X, W, K, S, and Q when used by inter.
__device__ __align__(256) hf g_Xh[(size_t)NROWS*DIM];
__device__ __align__(256) hf g_Wh[3*DD2];
__device__ __align__(256) hf g_Qh[(size_t)NROWS*DIM];
__device__ __align__(256) hf g_Ql[(size_t)NROWS*DIM];
__device__ __align__(256) hf g_Kh[(size_t)NROWS*DIM];
__device__ __align__(256) hf g_Vh[(size_t)NROWS*DIM];
__device__ __align__(256) hf g_Vl[(size_t)NROWS*DIM];
__device__ __align__(256) float g_U[(size_t)NG*DD2];
__device__ __align__(256) hf g_Sh[(size_t)NG*DD2];
__device__ __align__(256) hf g_Sch[(size_t)NG*GR2];
__device__ __align__(256) hf g_Scl[(size_t)NG*GR2];

#define POOL_BYTES 49152
#define ARR_BYTES  6144

// ---------------------------------------------------------------------------
// 128x128 GEMM core, fp16, BK=16, STAGES-deep cp.async pipeline.
//   SPLITA=true : A exact hi/lo pair -> 2 products (stage=18KB, STAGES=2)
//   SPLITA=false: A rounded once -> 1 product (stage=12KB, STAGES up to 4)
//   AT/BT select transposed-A (col_major) / NN-B (row_major) reads.
// 256 threads, 8 warps 2x4, warp tile 64x32 = 4x2 fragments.
// ---------------------------------------------------------------------------
template <int STAGES, bool AT, bool BT, bool SPLITA>
__device__ __forceinline__ void gemm_core(char* smpool,
    const hf* __restrict__ Ah, const hf* __restrict__ Al, size_t lda,
    const hf* __restrict__ Bh, size_t ldb,
    int nktp, AccFrag acc[4][2])
{
    constexpr int ALD = AT ? 136 : 24;   // AT tile: 16x136, else 128x24
    constexpr int BLD = BT ? 136 : 24;
    constexpr int NARR = SPLITA ? 3 : 2;
    constexpr int STAGE_BYTES = NARR * ARR_BYTES;
    constexpr int BOFF = (NARR - 1) * ARR_BYTES;
    static_assert(STAGES * STAGE_BYTES <= POOL_BYTES, "smem overflow");

    const int tid = threadIdx.x;
    const int w   = tid >> 5;
    const int wmi = w >> 2, wni = w & 3;

    // loader: each thread copies 1x16B per array per chunk
    const int ar  = AT ? (tid >> 4) : (tid >> 1);
    const int acb = (AT ? (tid & 15) : (tid & 1)) * 8;
    const int br  = BT ? (tid >> 4) : (tid >> 1);
    const int bcb = (BT ? (tid & 15) : (tid & 1)) * 8;
    const int aso = (ar * ALD + acb) * 2;   // byte offsets (16B aligned)
    const int bso = (br * BLD + bcb) * 2;

    auto agof = [&](int kt) -> size_t {
        return AT ? (size_t)(kt * 16 + ar) * lda + acb
                  : (size_t)ar * lda + kt * 16 + acb;
    };
    auto bgof = [&](int kt) -> size_t {
        return BT ? (size_t)(kt * 16 + br) * ldb + bcb
                  : (size_t)br * ldb + kt * 16 + bcb;
    };

    auto issue_copy = [&](int kt) {
        char* bb = smpool + (kt & (STAGES - 1)) * STAGE_BYTES;
        __pipeline_memcpy_async(bb + aso,             Ah + agof(kt), 16);
        if (SPLITA)
            __pipeline_memcpy_async(bb + ARR_BYTES + aso, Al + agof(kt), 16);
        __pipeline_memcpy_async(bb + BOFF + bso,      Bh + bgof(kt), 16);
        __pipeline_commit();
    };

#pragma unroll
    for (int mt = 0; mt < 4; mt++)
#pragma unroll
        for (int n2 = 0; n2 < 2; n2++)
            wm::fill_fragment(acc[mt][n2], 0.0f);

    using ALay = typename std::conditional<AT, wm::col_major, wm::row_major>::type;
    using BLay = typename std::conditional<BT, wm::row_major, wm::col_major>::type;

    for (int kt = 0; kt < STAGES - 1 && kt < nktp; ++kt)
        issue_copy(kt);

    for (int kt = 0; kt < nktp; ++kt) {
        {   // wait until chunk kt's copy is complete
            int rem = nktp - 1 - kt;          // copies issued after kt's
            int n = (STAGES - 2 < rem) ? STAGES - 2 : rem;
            if (n <= 0)      __pipeline_wait_prior(0);
            else if (n == 1) __pipeline_wait_prior(1);
            else if (n == 2) __pipeline_wait_prior(2);
            else             __pipeline_wait_prior(3);
        }
        __syncthreads();            // all warps done with the reused buffer
        if (kt + STAGES - 1 < nktp) // deep prefetch overlaps MMAs below
            issue_copy(kt + STAGES - 1);

        char* bb = smpool + (kt & (STAGES - 1)) * STAGE_BYTES;
        hf* Ash = (hf*)(bb);
        hf* Asl = (hf*)(bb + ARR_BYTES);
        hf* Bsh = (hf*)(bb + BOFF);

        wm::fragment<wm::matrix_b, 16, 16, 16, hf, BLay> bfh[2];
#pragma unroll
        for (int n2 = 0; n2 < 2; n2++) {
            int n0 = wni * 32 + n2 * 16;
            int off = BT ? n0 : n0 * BLD;
            wm::load_matrix_sync(bfh[n2], &Bsh[off], BLD);
        }
#pragma unroll
        for (int mt = 0; mt < 4; mt++) {
            wm::fragment<wm::matrix_a, 16, 16, 16, hf, ALay> afh, afl;
            int m0 = wmi * 64 + mt * 16;
            int off = AT ? m0 : m0 * ALD;
            wm::load_matrix_sync(afh, &Ash[off], ALD);
            if (SPLITA) wm::load_matrix_sync(afl, &Asl[off], ALD);
#pragma unroll
            for (int n2 = 0; n2 < 2; n2++) {
                wm::mma_sync(acc[mt][n2], afh, bfh[n2], acc[mt][n2]);
                if (SPLITA)
                    wm::mma_sync(acc[mt][n2], afl, bfh[n2], acc[mt][n2]);
            }
        }
    }
    __syncthreads();   // protect pool before epilogue aliases it
}

// Epilogue: stage each frag through smem (aliases pool), then scalar writes.
// Exposes: row (0..127 tile-local), col (0..127 tile-local), v (float).
#define EPILOGUE(...)                                                     \
  { float* stg = (float*)(smpool) + (threadIdx.x >> 5) * 320;             \
    const int lane = threadIdx.x & 31;                                    \
    const int w = threadIdx.x >> 5, wm_ = w >> 2, wn_ = w & 3;            \
    for (int mt = 0; mt < 4; mt++)                                        \
      for (int n2 = 0; n2 < 2; n2++) {                                    \
        wm::store_matrix_sync(stg, acc[mt][n2], 20, wm::mem_row_major);   \
        __syncwarp();                                                     \
        _Pragma("unroll")                                                 \
        for (int e = 0; e < 8; e++) {                                     \
          int lr = 2 * e + (lane >> 4); int lc = lane & 15;               \
          int row = wm_ * 64 + mt * 16 + lr;                              \
          int col = wn_ * 32 + n2 * 16 + lc;                              \
          float v = stg[lr * 20 + lc];                                    \
          __VA_ARGS__                                                     \
        }                                                                 \
        __syncwarp();                                                     \
      } }

#define DECL_POOL __shared__ __align__(16) char smpool[POOL_BYTES]

__device__ __forceinline__ void split1(hf* Oh, hf* Ol, size_t idx, float v) {
    hf h = __float2half_rn(v);
    Oh[idx] = h;
    Ol[idx] = __float2half_rn(v - __half2float(h));
}

// ---------------- conversion / scan ----------------------------------------
__global__ void conv_x_kernel(const float* __restrict__ x) {
    int i = blockIdx.x * 256 + threadIdx.x;       // over NROWS*DIM/4
    int r = i >> 7;
    int d = (i & 127) * 4;
    int tt = r >> 4, bb = r & 15;
    float4 v = *(const float4*)(x + (size_t)(bb * TLEN + tt) * DIM + d);
    size_t o = (size_t)r * DIM + d;
    g_Xh[o]     = __float2half_rn(v.x);
    g_Xh[o + 1] = __float2half_rn(v.y);
    g_Xh[o + 2] = __float2half_rn(v.z);
    g_Xh[o + 3] = __float2half_rn(v.w);
}

__global__ void conv_w_kernel(const float* __restrict__ Wq,
                              const float* __restrict__ Wk,
                              const float* __restrict__ Wv) {
    int i = blockIdx.x * 256 + threadIdx.x;       // over 3*DD2/4
    int z = i >> 16;
    int off = (i & 65535) * 4;
    const float* src = (z == 0) ? Wq : (z == 1) ? Wk : Wv;
    float4 v = *(const float4*)(src + off);
    size_t o = (size_t)z * DD2 + off;
    g_Wh[o]     = __float2half_rn(v.x);
    g_Wh[o + 1] = __float2half_rn(v.y);
    g_Wh[o + 2] = __float2half_rn(v.z);
    g_Wh[o + 3] = __float2half_rn(v.w);
}

__global__ void scan_kernel(const float* __restrict__ mem0) {
    int idx = blockIdx.x * 256 + threadIdx.x;     // over DD2 (scalar)
    float acc = mem0[idx];
    for (int g = 0; g < NG; g++) {
        size_t off = (size_t)g * DD2 + idx;
        float u = g_U[off];
        g_Sh[off] = __float2half_rn(acc);
        acc = fmaf(LRW, u, acc);
    }
}

// ---------------- GEMM kernels ---------------------------------------------
// QKV: single product, 4-stage pipeline (dominant stage).
__global__ __launch_bounds__(256, 2) void gemm_qkv_kernel() {
    DECL_POOL;
    int mt0 = blockIdx.x, nt0 = blockIdx.y, z = blockIdx.z;
    const hf* Ah = g_Xh + (size_t)mt0 * 128 * DIM;
    const hf* Bh = g_Wh + (size_t)z * DD2 + (size_t)nt0 * 128 * DIM;
    AccFrag acc[4][2];
    gemm_core<4, false, false, false>(smpool, Ah, nullptr, DIM, Bh, DIM,
                                      DIM / 16, acc);
    if (z == 1) {          // K: B-side only, single fp16
        EPILOGUE(
            g_Kh[(size_t)(mt0 * 128 + row) * DIM + nt0 * 128 + col] =
                __float2half_rn(v);
        )
    } else {               // Q, V: split for downstream A-side use
        hf* Oh = (z == 0) ? g_Qh : g_Vh;
        hf* Ol = (z == 0) ? g_Ql : g_Vl;
        EPILOGUE(
            size_t idx = (size_t)(mt0 * 128 + row) * DIM + nt0 * 128 + col;
            split1(Oh, Ol, idx, v);
        )
    }
}

// U_g[d,e] = sum_r V[r,d] K[r,e]   -- A = V read transposed, B = K read NN
__global__ __launch_bounds__(256, 2) void gemm_u_kernel() {
    DECL_POOL;
    int d0 = blockIdx.x * 128, e0 = blockIdx.y * 128, g = blockIdx.z;
    const hf* Ah = g_Vh + (size_t)(g * GROWS) * DIM + d0;
    const hf* Al = g_Vl + (size_t)(g * GROWS) * DIM + d0;
    const hf* Bh = g_Kh + (size_t)(g * GROWS) * DIM + e0;
    AccFrag acc[4][2];
    gemm_core<2, true, true, true>(smpool, Ah, Al, DIM, Bh, DIM,
                                   GROWS / 16, acc);
    float* U = g_U + (size_t)g * DD2;
    EPILOGUE(
        U[(size_t)(d0 + row) * DIM + e0 + col] = v;
    )
}

// inter: single product (Q rounded once here), 4-stage pipeline.
__global__ __launch_bounds__(256, 2) void gemm_inter_kernel(float* __restrict__ out) {
    DECL_POOL;
    int mt0 = blockIdx.x, nt0 = blockIdx.y;
    int g = mt0 >> 1;
    const hf* Ah = g_Qh + (size_t)mt0 * 128 * DIM;
    const hf* Bh = g_Sh + (size_t)g * DD2 + (size_t)nt0 * 128 * DIM;
    AccFrag acc[4][2];
    gemm_core<4, false, false, false>(smpool, Ah, nullptr, DIM, Bh, DIM,
                                      DIM / 16, acc);
    EPILOGUE(
        int r = mt0 * 128 + row;
        int tt = r >> 4; int bb = r & 15;
        out[(size_t)(bb * TLEN + tt) * DIM + nt0 * 128 + col] = v;
    )
}

__global__ __launch_bounds__(256, 2) void gemm_score_kernel() {
    DECL_POOL;
    int id = blockIdx.x;                 // 0:(0,0) 1:(1,0) 2:(1,1)
    int ti = (id == 0) ? 0 : 1;
    int tj = (id == 2) ? 1 : 0;
    int g = blockIdx.y;
    const hf* Ah = g_Qh + (size_t)(g * GROWS + ti * 128) * DIM;
    const hf* Al = g_Ql + (size_t)(g * GROWS + ti * 128) * DIM;
    const hf* Bh = g_Kh + (size_t)(g * GROWS + tj * 128) * DIM;
    AccFrag acc[4][2];
    gemm_core<2, false, false, true>(smpool, Ah, Al, DIM, Bh, DIM,
                                     DIM / 16, acc);
    hf* Sch = g_Sch + (size_t)g * GR2;
    hf* Scl = g_Scl + (size_t)g * GR2;
    EPILOGUE(
        int rr = ti * 128 + row;
        int ss = tj * 128 + col;
        float m = ((ss >> 4) <= (rr >> 4)) ? LRW * v : 0.0f;
        split1(Sch, Scl, (size_t)rr * GROWS + ss, m);
    )
}

// out[r,d] += sum_s Sc[r,s] V[s,d]  -- B = V read NN
__global__ __launch_bounds__(256, 2) void gemm_av_kernel(float* __restrict__ out) {
    DECL_POOL;
    int ti = blockIdx.x;                 // 0..1 row tile within group
    int nt0 = blockIdx.y;                // 0..3
    int g = blockIdx.z;
    const hf* Ah = g_Sch + (size_t)g * GR2 + (size_t)ti * 128 * GROWS;
    const hf* Al = g_Scl + (size_t)g * GR2 + (size_t)ti * 128 * GROWS;
    const hf* Bh = g_Vh + (size_t)(g * GROWS) * DIM + nt0 * 128;
    AccFrag acc[4][2];
    gemm_core<2, false, true, true>(smpool, Ah, Al, GROWS, Bh, DIM,
                                    8 * (ti + 1), acc);
    EPILOGUE(
        int r = g * GROWS + ti * 128 + row;
        int tt = r >> 4; int bb = r & 15;
        size_t idx = (size_t)(bb * TLEN + tt) * DIM + nt0 * 128 + col;
        out[idx] += v;
    )
}

// ---------------------------------------------------------------------------
extern "C" void kernel_launch(void* const* d_in, const int* in_sizes, int n_in,
                              void* d_out, int out_size) {
    (void)in_sizes; (void)n_in; (void)out_size;
    const float* x  = (const float*)d_in[0];
    const float* Wq = (const float*)d_in[1];
    const float* Wk = (const float*)d_in[2];
    const float* Wv = (const float*)d_in[3];
    const float* m0 = (const float*)d_in[4];
    float* out = (float*)d_out;

    conv_x_kernel<<<32768, 256>>>(x);
    conv_w_kernel<<<768, 256>>>(Wq, Wk, Wv);
    gemm_qkv_kernel<<<dim3(512, 4, 3), 256>>>();
    gemm_u_kernel<<<dim3(4, 4, 256), 256>>>();
    scan_kernel<<<1024, 256>>>(m0);
    gemm_score_kernel<<<dim3(3, 256), 256>>>();
    gemm_inter_kernel<<<dim3(512, 4), 256>>>(out);
    gemm_av_kernel<<<dim3(2, 4, 256), 256>>>(out);
}

// round 17
// speedup vs baseline: 4.2732x; 1.2018x over previous
#include <cuda_runtime.h>
#include <cuda_fp16.h>
#include <cuda_pipeline.h>
#include <mma.h>
#include <cstdint>
#include <type_traits>

typedef __half hf;
namespace wm = nvcuda::wmma;
using AccFrag = wm::fragment<wm::accumulator, 16, 16, 16, float>;

#define BATCH 16
#define TLEN  4096
#define DIM   512
#define NROWS 65536              // time-major rows r = t*16 + b
#define GROWS 256                // rows per group (16 t-steps x 16 batch)
#define NG    256
#define DD2   (DIM*DIM)          // 262144
#define GR2   (GROWS*GROWS)
#define LRW   0.01f

// ---------------- device scratch (all operands rounded once to fp16) -------
__device__ __align__(256) hf g_Xh[(size_t)NROWS*DIM];
__device__ __align__(256) hf g_Wh[3*DD2];
__device__ __align__(256) hf g_Qh[(size_t)NROWS*DIM];
__device__ __align__(256) hf g_Kh[(size_t)NROWS*DIM];
__device__ __align__(256) hf g_Vh[(size_t)NROWS*DIM];
__device__ __align__(256) float g_U[(size_t)NG*DD2];
__device__ __align__(256) hf g_Sh[(size_t)NG*DD2];
__device__ __align__(256) hf g_Sch[(size_t)NG*GR2];

#define POOL_BYTES 49152

// ---------------------------------------------------------------------------
// 128x128 GEMM core, fp16 single product, BK=16, STAGES-deep cp.async
// pipeline (4 stages fit for every layout now that operands are unsplit).
//   AT=false: A stored [m][k] k-contig (row_major frag), tile 128x24 = 6KB
//   AT=true : A stored [k][m] m-contig (col_major frag), tile 16x136 = 4.25KB
//   BT likewise for B (NT vs NN).
// 256 threads, 8 warps 2x4, warp tile 64x32 = 4x2 fragments.
// ---------------------------------------------------------------------------
template <int STAGES, bool AT, bool BT>
__device__ __forceinline__ void gemm_core(char* smpool,
    const hf* __restrict__ Ah, size_t lda,
    const hf* __restrict__ Bh, size_t ldb,
    int nktp, AccFrag acc[4][2])
{
    constexpr int ALD = AT ? 136 : 24;
    constexpr int BLD = BT ? 136 : 24;
    constexpr int ABYTES = AT ? 4352 : 6144;
    constexpr int BBYTES = BT ? 4352 : 6144;
    constexpr int STAGE_BYTES = ABYTES + BBYTES;
    static_assert(STAGES * STAGE_BYTES <= POOL_BYTES, "smem overflow");

    const int tid = threadIdx.x;
    const int w   = tid >> 5;
    const int wmi = w >> 2, wni = w & 3;

    // loader: each thread copies 1x16B per array per chunk
    const int ar  = AT ? (tid >> 4) : (tid >> 1);
    const int acb = (AT ? (tid & 15) : (tid & 1)) * 8;
    const int br  = BT ? (tid >> 4) : (tid >> 1);
    const int bcb = (BT ? (tid & 15) : (tid & 1)) * 8;
    const int aso = (ar * ALD + acb) * 2;   // byte offsets (16B aligned)
    const int bso = (br * BLD + bcb) * 2;

    auto agof = [&](int kt) -> size_t {
        return AT ? (size_t)(kt * 16 + ar) * lda + acb
                  : (size_t)ar * lda + kt * 16 + acb;
    };
    auto bgof = [&](int kt) -> size_t {
        return BT ? (size_t)(kt * 16 + br) * ldb + bcb
                  : (size_t)br * ldb + kt * 16 + bcb;
    };

    auto issue_copy = [&](int kt) {
        char* bb = smpool + (kt & (STAGES - 1)) * STAGE_BYTES;
        __pipeline_memcpy_async(bb + aso,          Ah + agof(kt), 16);
        __pipeline_memcpy_async(bb + ABYTES + bso, Bh + bgof(kt), 16);
        __pipeline_commit();
    };

#pragma unroll
    for (int mt = 0; mt < 4; mt++)
#pragma unroll
        for (int n2 = 0; n2 < 2; n2++)
            wm::fill_fragment(acc[mt][n2], 0.0f);

    using ALay = typename std::conditional<AT, wm::col_major, wm::row_major>::type;
    using BLay = typename std::conditional<BT, wm::row_major, wm::col_major>::type;

    for (int kt = 0; kt < STAGES - 1 && kt < nktp; ++kt)
        issue_copy(kt);

    for (int kt = 0; kt < nktp; ++kt) {
        {   // wait until chunk kt's copy is complete
            int rem = nktp - 1 - kt;          // copies issued after kt's
            int n = (STAGES - 2 < rem) ? STAGES - 2 : rem;
            if (n <= 0)      __pipeline_wait_prior(0);
            else if (n == 1) __pipeline_wait_prior(1);
            else if (n == 2) __pipeline_wait_prior(2);
            else             __pipeline_wait_prior(3);
        }
        __syncthreads();            // all warps done with the reused buffer
        if (kt + STAGES - 1 < nktp) // deep prefetch overlaps MMAs below
            issue_copy(kt + STAGES - 1);

        char* bb = smpool + (kt & (STAGES - 1)) * STAGE_BYTES;
        hf* Ash = (hf*)(bb);
        hf* Bsh = (hf*)(bb + ABYTES);

        wm::fragment<wm::matrix_b, 16, 16, 16, hf, BLay> bfh[2];
#pragma unroll
        for (int n2 = 0; n2 < 2; n2++) {
            int n0 = wni * 32 + n2 * 16;
            int off = BT ? n0 : n0 * BLD;
            wm::load_matrix_sync(bfh[n2], &Bsh[off], BLD);
        }
#pragma unroll
        for (int mt = 0; mt < 4; mt++) {
            wm::fragment<wm::matrix_a, 16, 16, 16, hf, ALay> afh;
            int m0 = wmi * 64 + mt * 16;
            int off = AT ? m0 : m0 * ALD;
            wm::load_matrix_sync(afh, &Ash[off], ALD);
#pragma unroll
            for (int n2 = 0; n2 < 2; n2++)
                wm::mma_sync(acc[mt][n2], afh, bfh[n2], acc[mt][n2]);
        }
    }
    __syncthreads();   // protect pool before epilogue aliases it
}

// Epilogue: stage each frag through smem (aliases pool), then scalar writes.
// Exposes: row (0..127 tile-local), col (0..127 tile-local), v (float).
#define EPILOGUE(...)                                                     \
  { float* stg = (float*)(smpool) + (threadIdx.x >> 5) * 320;             \
    const int lane = threadIdx.x & 31;                                    \
    const int w = threadIdx.x >> 5, wm_ = w >> 2, wn_ = w & 3;            \
    for (int mt = 0; mt < 4; mt++)                                        \
      for (int n2 = 0; n2 < 2; n2++) {                                    \
        wm::store_matrix_sync(stg, acc[mt][n2], 20, wm::mem_row_major);   \
        __syncwarp();                                                     \
        _Pragma("unroll")                                                 \
        for (int e = 0; e < 8; e++) {                                     \
          int lr = 2 * e + (lane >> 4); int lc = lane & 15;               \
          int row = wm_ * 64 + mt * 16 + lr;                              \
          int col = wn_ * 32 + n2 * 16 + lc;                              \
          float v = stg[lr * 20 + lc];                                    \
          __VA_ARGS__                                                     \
        }                                                                 \
        __syncwarp();                                                     \
      } }

#define DECL_POOL __shared__ __align__(16) char smpool[POOL_BYTES]

// ---------------- conversion / scan ----------------------------------------
__global__ void conv_x_kernel(const float* __restrict__ x) {
    int i = blockIdx.x * 256 + threadIdx.x;       // over NROWS*DIM/4
    int r = i >> 7;
    int d = (i & 127) * 4;
    int tt = r >> 4, bb = r & 15;
    float4 v = *(const float4*)(x + (size_t)(bb * TLEN + tt) * DIM + d);
    size_t o = (size_t)r * DIM + d;
    g_Xh[o]     = __float2half_rn(v.x);
    g_Xh[o + 1] = __float2half_rn(v.y);
    g_Xh[o + 2] = __float2half_rn(v.z);
    g_Xh[o + 3] = __float2half_rn(v.w);
}

__global__ void conv_w_kernel(const float* __restrict__ Wq,
                              const float* __restrict__ Wk,
                              const float* __restrict__ Wv) {
    int i = blockIdx.x * 256 + threadIdx.x;       // over 3*DD2/4
    int z = i >> 16;
    int off = (i & 65535) * 4;
    const float* src = (z == 0) ? Wq : (z == 1) ? Wk : Wv;
    float4 v = *(const float4*)(src + off);
    size_t o = (size_t)z * DD2 + off;
    g_Wh[o]     = __float2half_rn(v.x);
    g_Wh[o + 1] = __float2half_rn(v.y);
    g_Wh[o + 2] = __float2half_rn(v.z);
    g_Wh[o + 3] = __float2half_rn(v.w);
}

__global__ void scan_kernel(const float* __restrict__ mem0) {
    int idx = blockIdx.x * 256 + threadIdx.x;     // over DD2 (scalar)
    float acc = mem0[idx];
    for (int g = 0; g < NG; g++) {
        size_t off = (size_t)g * DD2 + idx;
        float u = g_U[off];
        g_Sh[off] = __float2half_rn(acc);
        acc = fmaf(LRW, u, acc);
    }
}

// ---------------- GEMM kernels ---------------------------------------------
__global__ __launch_bounds__(256, 2) void gemm_qkv_kernel() {
    DECL_POOL;
    int mt0 = blockIdx.x, nt0 = blockIdx.y, z = blockIdx.z;
    const hf* Ah = g_Xh + (size_t)mt0 * 128 * DIM;
    const hf* Bh = g_Wh + (size_t)z * DD2 + (size_t)nt0 * 128 * DIM;
    AccFrag acc[4][2];
    gemm_core<4, false, false>(smpool, Ah, DIM, Bh, DIM, DIM / 16, acc);
    hf* O = (z == 0) ? g_Qh : (z == 1) ? g_Kh : g_Vh;
    EPILOGUE(
        O[(size_t)(mt0 * 128 + row) * DIM + nt0 * 128 + col] =
            __float2half_rn(v);
    )
}

// U_g[d,e] = sum_r V[r,d] K[r,e]   -- A = V read transposed, B = K read NN
__global__ __launch_bounds__(256, 2) void gemm_u_kernel() {
    DECL_POOL;
    int d0 = blockIdx.x * 128, e0 = blockIdx.y * 128, g = blockIdx.z;
    const hf* Ah = g_Vh + (size_t)(g * GROWS) * DIM + d0;
    const hf* Bh = g_Kh + (size_t)(g * GROWS) * DIM + e0;
    AccFrag acc[4][2];
    gemm_core<4, true, true>(smpool, Ah, DIM, Bh, DIM, GROWS / 16, acc);
    float* U = g_U + (size_t)g * DD2;
    EPILOGUE(
        U[(size_t)(d0 + row) * DIM + e0 + col] = v;
    )
}

__global__ __launch_bounds__(256, 2) void gemm_inter_kernel(float* __restrict__ out) {
    DECL_POOL;
    int mt0 = blockIdx.x, nt0 = blockIdx.y;
    int g = mt0 >> 1;
    const hf* Ah = g_Qh + (size_t)mt0 * 128 * DIM;
    const hf* Bh = g_Sh + (size_t)g * DD2 + (size_t)nt0 * 128 * DIM;
    AccFrag acc[4][2];
    gemm_core<4, false, false>(smpool, Ah, DIM, Bh, DIM, DIM / 16, acc);
    EPILOGUE(
        int r = mt0 * 128 + row;
        int tt = r >> 4; int bb = r & 15;
        out[(size_t)(bb * TLEN + tt) * DIM + nt0 * 128 + col] = v;
    )
}

__global__ __launch_bounds__(256, 2) void gemm_score_kernel() {
    DECL_POOL;
    int id = blockIdx.x;                 // 0:(0,0) 1:(1,0) 2:(1,1)
    int ti = (id == 0) ? 0 : 1;
    int tj = (id == 2) ? 1 : 0;
    int g = blockIdx.y;
    const hf* Ah = g_Qh + (size_t)(g * GROWS + ti * 128) * DIM;
    const hf* Bh = g_Kh + (size_t)(g * GROWS + tj * 128) * DIM;
    AccFrag acc[4][2];
    gemm_core<4, false, false>(smpool, Ah, DIM, Bh, DIM, DIM / 16, acc);
    hf* Sch = g_Sch + (size_t)g * GR2;
    EPILOGUE(
        int rr = ti * 128 + row;
        int ss = tj * 128 + col;
        float m = ((ss >> 4) <= (rr >> 4)) ? LRW * v : 0.0f;
        Sch[(size_t)rr * GROWS + ss] = __float2half_rn(m);
    )
}

// out[r,d] += sum_s Sc[r,s] V[s,d]  -- B = V read NN
__global__ __launch_bounds__(256, 2) void gemm_av_kernel(float* __restrict__ out) {
    DECL_POOL;
    int ti = blockIdx.x;                 // 0..1 row tile within group
    int nt0 = blockIdx.y;                // 0..3
    int g = blockIdx.z;
    const hf* Ah = g_Sch + (size_t)g * GR2 + (size_t)ti * 128 * GROWS;
    const hf* Bh = g_Vh + (size_t)(g * GROWS) * DIM + nt0 * 128;
    AccFrag acc[4][2];
    gemm_core<4, false, true>(smpool, Ah, GROWS, Bh, DIM, 8 * (ti + 1), acc);
    EPILOGUE(
        int r = g * GROWS + ti * 128 + row;
        int tt = r >> 4; int bb = r & 15;
        size_t idx = (size_t)(bb * TLEN + tt) * DIM + nt0 * 128 + col;
        out[idx] += v;
    )
}

// ---------------------------------------------------------------------------
extern "C" void kernel_launch(void* const* d_in, const int* in_sizes, int n_in,
                              void* d_out, int out_size) {
    (void)in_sizes; (void)n_in; (void)out_size;
    const float* x  = (const float*)d_in[0];
    const float* Wq = (const float*)d_in[1];
    const float* Wk = (const float*)d_in[2];
    const float* Wv = (const float*)d_in[3];
    const float* m0 = (const float*)d_in[4];
    float* out = (float*)d_out;

    conv_x_kernel<<<32768, 256>>>(x);
    conv_w_kernel<<<768, 256>>>(Wq, Wk, Wv);
    gemm_qkv_kernel<<<dim3(512, 4, 3), 256>>>();
    gemm_u_kernel<<<dim3(4, 4, 256), 256>>>();
    scan_kernel<<<1024, 256>>>(m0);
    gemm_score_kernel<<<dim3(3, 256), 256>>>();
    gemm_inter_kernel<<<dim3(512, 4), 256>>>(out);
    gemm_av_kernel<<<dim3(2, 4, 256), 256>>>(out);
}